// round 3
// baseline (speedup 1.0000x reference)
#include <cuda_runtime.h>
#include <cstdint>

// ---------------------------------------------------------------------------
// TwoWordPSDProbe: out[b,i,j] = max(||t_i||^2 + ||t_j||^2 - 2 t_i.t_j, 0)
// where t = batch @ proj.  B=16, S=1024, D=1024, R=128.
//
// Strategy: tf32 mma.sync for both GEMMs. t is stored tf32-rounded; norms are
// computed from the SAME rounded values so the diagonal is consistent.
// ---------------------------------------------------------------------------

#define BATCH 16
#define SEQ   1024
#define DIM   1024
#define RANK  128

// scratch: t (tf32-rounded, stored as f32 bit patterns) and row norms
static __device__ __align__(16) float g_t[BATCH * SEQ * RANK];      // 8 MB
static __device__ float g_norms[BATCH * SEQ];                        // 64 KB

__device__ __forceinline__ unsigned tf32r(float x) {
    unsigned y;
    asm("cvt.rna.tf32.f32 %0, %1;" : "=r"(y) : "f"(x));
    return y;
}

__device__ __forceinline__ void mma_tf32(float& d0, float& d1, float& d2, float& d3,
                                         unsigned a0, unsigned a1, unsigned a2, unsigned a3,
                                         unsigned b0, unsigned b1) {
    asm volatile(
        "mma.sync.aligned.m16n8k8.row.col.f32.tf32.tf32.f32 "
        "{%0,%1,%2,%3}, {%4,%5,%6,%7}, {%8,%9}, {%0,%1,%2,%3};"
        : "+f"(d0), "+f"(d1), "+f"(d2), "+f"(d3)
        : "r"(a0), "r"(a1), "r"(a2), "r"(a3), "r"(b0), "r"(b1));
}

// smem leading dim (floats). 36 -> fragment read bank = (4g+tg)%32, conflict-free.
#define LDS_A 36

// ---------------------------------------------------------------------------
// Kernel 1: t = batch @ proj   (M=16384, N=128, K=1024)
// CTA tile 128x128 (full N), K chunks of 32. 8 warps = 4(m) x 2(n), warp 32x64.
// ---------------------------------------------------------------------------
__global__ __launch_bounds__(256) void gemm1_kernel(const float* __restrict__ batch,
                                                    const float* __restrict__ proj) {
    __shared__ __align__(16) float sA[128 * LDS_A];   // [row][k]
    __shared__ __align__(16) float sB[128 * LDS_A];   // [n][k]

    const int tid  = threadIdx.x;
    const int warp = tid >> 5, lane = tid & 31;
    const int wm = warp >> 1, wn = warp & 1;          // 4 x 2 warp grid
    const int g  = lane >> 2, tg = lane & 3;
    const int m0 = blockIdx.x * 128;

    float acc[2][8][4];
#pragma unroll
    for (int mt = 0; mt < 2; mt++)
#pragma unroll
        for (int nt = 0; nt < 8; nt++)
#pragma unroll
            for (int v = 0; v < 4; v++) acc[mt][nt][v] = 0.0f;

    for (int k0 = 0; k0 < DIM; k0 += 32) {
        // load A chunk: 128 rows x 32 k (tf32-rounded)
#pragma unroll
        for (int i = 0; i < 4; i++) {
            int row = (tid >> 3) + i * 32;
            int kk  = (tid & 7) * 4;
            float4 v = *(const float4*)(batch + (size_t)(m0 + row) * DIM + k0 + kk);
            v.x = __uint_as_float(tf32r(v.x));
            v.y = __uint_as_float(tf32r(v.y));
            v.z = __uint_as_float(tf32r(v.z));
            v.w = __uint_as_float(tf32r(v.w));
            *(float4*)(&sA[row * LDS_A + kk]) = v;
        }
        // load B chunk: proj[k0+k][n] -> sB[n][k] (transposed, tf32-rounded)
#pragma unroll
        for (int i = 0; i < 4; i++) {
            int kk = (tid >> 5) + i * 8;
            int nn = (lane) * 4;
            float4 v = *(const float4*)(proj + (size_t)(k0 + kk) * RANK + nn);
            sB[(nn + 0) * LDS_A + kk] = __uint_as_float(tf32r(v.x));
            sB[(nn + 1) * LDS_A + kk] = __uint_as_float(tf32r(v.y));
            sB[(nn + 2) * LDS_A + kk] = __uint_as_float(tf32r(v.z));
            sB[(nn + 3) * LDS_A + kk] = __uint_as_float(tf32r(v.w));
        }
        __syncthreads();

#pragma unroll
        for (int ks = 0; ks < 4; ks++) {
            const int kb = ks * 8;
            unsigned a[2][4];
#pragma unroll
            for (int mt = 0; mt < 2; mt++) {
                int row = wm * 32 + mt * 16;
                a[mt][0] = __float_as_uint(sA[(row + g    ) * LDS_A + kb + tg    ]);
                a[mt][1] = __float_as_uint(sA[(row + g + 8) * LDS_A + kb + tg    ]);
                a[mt][2] = __float_as_uint(sA[(row + g    ) * LDS_A + kb + tg + 4]);
                a[mt][3] = __float_as_uint(sA[(row + g + 8) * LDS_A + kb + tg + 4]);
            }
            unsigned bfr[8][2];
#pragma unroll
            for (int nt = 0; nt < 8; nt++) {
                int col = wn * 64 + nt * 8;
                bfr[nt][0] = __float_as_uint(sB[(col + g) * LDS_A + kb + tg    ]);
                bfr[nt][1] = __float_as_uint(sB[(col + g) * LDS_A + kb + tg + 4]);
            }
#pragma unroll
            for (int mt = 0; mt < 2; mt++)
#pragma unroll
                for (int nt = 0; nt < 8; nt++)
                    mma_tf32(acc[mt][nt][0], acc[mt][nt][1], acc[mt][nt][2], acc[mt][nt][3],
                             a[mt][0], a[mt][1], a[mt][2], a[mt][3],
                             bfr[nt][0], bfr[nt][1]);
        }
        __syncthreads();
    }

    // epilogue: round t to tf32 and store
#pragma unroll
    for (int mt = 0; mt < 2; mt++) {
#pragma unroll
        for (int nt = 0; nt < 8; nt++) {
            int row = m0 + wm * 32 + mt * 16 + g;
            int col = wn * 64 + nt * 8 + tg * 2;
            float2 lo, hi;
            lo.x = __uint_as_float(tf32r(acc[mt][nt][0]));
            lo.y = __uint_as_float(tf32r(acc[mt][nt][1]));
            hi.x = __uint_as_float(tf32r(acc[mt][nt][2]));
            hi.y = __uint_as_float(tf32r(acc[mt][nt][3]));
            *(float2*)(&g_t[(size_t)row * RANK + col])       = lo;
            *(float2*)(&g_t[(size_t)(row + 8) * RANK + col]) = hi;
        }
    }
}

// ---------------------------------------------------------------------------
// Kernel 2: row norms of t (from the tf32-rounded values)
// One warp per row.
// ---------------------------------------------------------------------------
__global__ __launch_bounds__(256) void norms_kernel() {
    int row  = blockIdx.x * 8 + (threadIdx.x >> 5);
    int lane = threadIdx.x & 31;
    float4 v = *(const float4*)(g_t + (size_t)row * RANK + lane * 4);
    float s = v.x * v.x + v.y * v.y + v.z * v.z + v.w * v.w;
#pragma unroll
    for (int off = 16; off > 0; off >>= 1)
        s += __shfl_xor_sync(0xFFFFFFFFu, s, off);
    if (lane == 0) g_norms[row] = s;
}

// ---------------------------------------------------------------------------
// Kernel 3: out[b,i,j] = max(n_i + n_j - 2 * t_i . t_j, 0)
// Per-batch 1024x1024x128 GEMM. CTA tile 128x128, K chunks of 32.
// ---------------------------------------------------------------------------
__global__ __launch_bounds__(256) void gemm2_kernel(float* __restrict__ out) {
    __shared__ __align__(16) float sA[128 * LDS_A];
    __shared__ __align__(16) float sB[128 * LDS_A];
    __shared__ float nI[128], nJ[128];

    const int tid  = threadIdx.x;
    const int warp = tid >> 5, lane = tid & 31;
    const int wm = warp >> 1, wn = warp & 1;
    const int g  = lane >> 2, tg = lane & 3;

    const int b  = blockIdx.z;
    const int bi = blockIdx.y;
    const int bj = blockIdx.x;

    const float* tb = g_t + (size_t)b * SEQ * RANK;

    if (tid < 128)       nI[tid]       = g_norms[b * SEQ + bi * 128 + tid];
    else                 nJ[tid - 128] = g_norms[b * SEQ + bj * 128 + (tid - 128)];

    float acc[2][8][4];
#pragma unroll
    for (int mt = 0; mt < 2; mt++)
#pragma unroll
        for (int nt = 0; nt < 8; nt++)
#pragma unroll
            for (int v = 0; v < 4; v++) acc[mt][nt][v] = 0.0f;

    for (int k0 = 0; k0 < RANK; k0 += 32) {
#pragma unroll
        for (int i = 0; i < 4; i++) {
            int row = (tid >> 3) + i * 32;
            int kk  = (tid & 7) * 4;
            *(float4*)(&sA[row * LDS_A + kk]) =
                *(const float4*)(tb + (size_t)(bi * 128 + row) * RANK + k0 + kk);
            *(float4*)(&sB[row * LDS_A + kk]) =
                *(const float4*)(tb + (size_t)(bj * 128 + row) * RANK + k0 + kk);
        }
        __syncthreads();

#pragma unroll
        for (int ks = 0; ks < 4; ks++) {
            const int kb = ks * 8;
            unsigned a[2][4];
#pragma unroll
            for (int mt = 0; mt < 2; mt++) {
                int row = wm * 32 + mt * 16;
                a[mt][0] = __float_as_uint(sA[(row + g    ) * LDS_A + kb + tg    ]);
                a[mt][1] = __float_as_uint(sA[(row + g + 8) * LDS_A + kb + tg    ]);
                a[mt][2] = __float_as_uint(sA[(row + g    ) * LDS_A + kb + tg + 4]);
                a[mt][3] = __float_as_uint(sA[(row + g + 8) * LDS_A + kb + tg + 4]);
            }
            unsigned bfr[8][2];
#pragma unroll
            for (int nt = 0; nt < 8; nt++) {
                int col = wn * 64 + nt * 8;
                bfr[nt][0] = __float_as_uint(sB[(col + g) * LDS_A + kb + tg    ]);
                bfr[nt][1] = __float_as_uint(sB[(col + g) * LDS_A + kb + tg + 4]);
            }
#pragma unroll
            for (int mt = 0; mt < 2; mt++)
#pragma unroll
                for (int nt = 0; nt < 8; nt++)
                    mma_tf32(acc[mt][nt][0], acc[mt][nt][1], acc[mt][nt][2], acc[mt][nt][3],
                             a[mt][0], a[mt][1], a[mt][2], a[mt][3],
                             bfr[nt][0], bfr[nt][1]);
        }
        __syncthreads();
    }

    float* outb = out + (size_t)b * SEQ * SEQ;
#pragma unroll
    for (int mt = 0; mt < 2; mt++) {
#pragma unroll
        for (int nt = 0; nt < 8; nt++) {
            int r0 = wm * 32 + mt * 16 + g;
            int c  = wn * 64 + nt * 8 + tg * 2;
            float ni0 = nI[r0], ni1 = nI[r0 + 8];
            float nj0 = nJ[c],  nj1 = nJ[c + 1];
            float2 lo, hi;
            lo.x = fmaxf(ni0 + nj0 - 2.0f * acc[mt][nt][0], 0.0f);
            lo.y = fmaxf(ni0 + nj1 - 2.0f * acc[mt][nt][1], 0.0f);
            hi.x = fmaxf(ni1 + nj0 - 2.0f * acc[mt][nt][2], 0.0f);
            hi.y = fmaxf(ni1 + nj1 - 2.0f * acc[mt][nt][3], 0.0f);
            size_t base = (size_t)(bi * 128 + r0) * SEQ + bj * 128 + c;
            *(float2*)(&outb[base])                 = lo;
            *(float2*)(&outb[base + (size_t)8 * SEQ]) = hi;
        }
    }
}

// ---------------------------------------------------------------------------
extern "C" void kernel_launch(void* const* d_in, const int* in_sizes, int n_in,
                              void* d_out, int out_size) {
    const float* batch = (const float*)d_in[0];   // [16,1024,1024] f32
    const float* proj  = (const float*)d_in[1];   // [1024,128] f32
    float* out = (float*)d_out;                   // [16,1024,1024] f32
    (void)in_sizes; (void)n_in; (void)out_size;

    gemm1_kernel<<<128, 256>>>(batch, proj);
    norms_kernel<<<BATCH * SEQ / 8, 256>>>();
    gemm2_kernel<<<dim3(8, 8, BATCH), 256>>>(out);
}

// round 6
// speedup vs baseline: 1.5979x; 1.5979x over previous
#include <cuda_runtime.h>
#include <cstdint>

// ---------------------------------------------------------------------------
// TwoWordPSDProbe: out[b,i,j] = max(||t_i||^2 + ||t_j||^2 - 2 t_i.t_j, 0)
// where t = batch @ proj.  B=16, S=1024, D=1024, R=128.
//
// tf32 mma.sync both GEMMs. Inputs to gemm1 are EXPLICITLY rounded to tf32
// (cvt.rna) — HW truncation is biased and pushes rel_err to ~1.5e-3.
// t is stored tf32-rounded; norms come from the same rounded values.
// ---------------------------------------------------------------------------

#define BATCH 16
#define SEQ   1024
#define DIM   1024
#define RANK  128

static __device__ __align__(16) float g_t[BATCH * SEQ * RANK];      // 8 MB
static __device__ __align__(16) float g_projr[DIM * RANK];           // 512 KB, tf32-rounded proj
static __device__ float g_norms[BATCH * SEQ];                        // 64 KB

__device__ __forceinline__ unsigned tf32r(float x) {
    unsigned y;
    asm("cvt.rna.tf32.f32 %0, %1;" : "=r"(y) : "f"(x));
    return y;
}

__device__ __forceinline__ void mma_tf32(float& d0, float& d1, float& d2, float& d3,
                                         unsigned a0, unsigned a1, unsigned a2, unsigned a3,
                                         unsigned b0, unsigned b1) {
    asm volatile(
        "mma.sync.aligned.m16n8k8.row.col.f32.tf32.tf32.f32 "
        "{%0,%1,%2,%3}, {%4,%5,%6,%7}, {%8,%9}, {%0,%1,%2,%3};"
        : "+f"(d0), "+f"(d1), "+f"(d2), "+f"(d3)
        : "r"(a0), "r"(a1), "r"(a2), "r"(a3), "r"(b0), "r"(b1));
}

__device__ __forceinline__ void cp_async16(void* sptr, const void* gptr) {
    unsigned saddr = (unsigned)__cvta_generic_to_shared(sptr);
    asm volatile("cp.async.cg.shared.global [%0], [%1], 16;\n" :: "r"(saddr), "l"(gptr));
}
#define CP_COMMIT() asm volatile("cp.async.commit_group;\n")
#define CP_WAIT(N)  asm volatile("cp.async.wait_group %0;\n" :: "n"(N))

// ---------------------------------------------------------------------------
// Kernel 0: round proj to tf32 once (131072 elements).
// ---------------------------------------------------------------------------
__global__ __launch_bounds__(256) void round_proj_kernel(const float* __restrict__ proj) {
    int i = blockIdx.x * 256 + threadIdx.x;          // float4 index
    float4 v = ((const float4*)proj)[i];
    v.x = __uint_as_float(tf32r(v.x));
    v.y = __uint_as_float(tf32r(v.y));
    v.z = __uint_as_float(tf32r(v.z));
    v.w = __uint_as_float(tf32r(v.w));
    ((float4*)g_projr)[i] = v;
}

// ---------------------------------------------------------------------------
// Kernel 1: t = batch @ proj   (M=16384, N=128, K=1024)
// CTA tile 64x128 -> grid 256, 8 warps = 2(m) x 4(n), warp 32x32.
// A: LDG(+1 chunk ahead) -> cvt.rna -> STS, 2-stage smem.
// B: cp.async from pre-rounded g_projr, 2-stage smem, k-major pad 136.
// ---------------------------------------------------------------------------
#define S1_AS (64 * 36)
#define S1_BS (32 * 136)
#define S1_CHUNKS (DIM / 32)

__global__ __launch_bounds__(256, 2) void gemm1_kernel(const float* __restrict__ batch) {
    extern __shared__ float smem[];
    float* sA = smem;               // [2][64][36]
    float* sB = smem + 2 * S1_AS;   // [2][32][136]

    const int tid  = threadIdx.x;
    const int warp = tid >> 5, lane = tid & 31;
    const int wm = warp >> 2, wn = warp & 3;      // 2 x 4 warp grid
    const int g  = lane >> 2, tg = lane & 3;
    const int m0 = blockIdx.x * 64;

    float acc[2][4][4];
#pragma unroll
    for (int mt = 0; mt < 2; mt++)
#pragma unroll
        for (int nt = 0; nt < 4; nt++)
#pragma unroll
            for (int v = 0; v < 4; v++) acc[mt][nt][v] = 0.0f;

    const int a_row0 = tid >> 3, a_kk = (tid & 7) * 4;   // 2 rows/thread
    const int b_kr0  = tid >> 5, b_nn = lane * 4;

    const float* aptr0 = batch + (size_t)(m0 + a_row0) * DIM + a_kk;
    const float* aptr1 = batch + (size_t)(m0 + a_row0 + 32) * DIM + a_kk;

    float4 rcur0, rcur1, rnx0, rnx1;

    auto ldg_a = [&](int c, float4& r0, float4& r1) {
        r0 = *(const float4*)(aptr0 + c * 32);
        r1 = *(const float4*)(aptr1 + c * 32);
    };
    auto sts_a = [&](const float4& r0, const float4& r1, int s) {
        float* a = sA + s * S1_AS;
        float4 v0, v1;
        v0.x = __uint_as_float(tf32r(r0.x)); v0.y = __uint_as_float(tf32r(r0.y));
        v0.z = __uint_as_float(tf32r(r0.z)); v0.w = __uint_as_float(tf32r(r0.w));
        v1.x = __uint_as_float(tf32r(r1.x)); v1.y = __uint_as_float(tf32r(r1.y));
        v1.z = __uint_as_float(tf32r(r1.z)); v1.w = __uint_as_float(tf32r(r1.w));
        *(float4*)(&a[a_row0 * 36 + a_kk])        = v0;
        *(float4*)(&a[(a_row0 + 32) * 36 + a_kk]) = v1;
    };
    auto cp_b = [&](int c) {
        float* b = sB + (c & 1) * S1_BS;
        const int k0 = c * 32;
#pragma unroll
        for (int i = 0; i < 4; i++) {
            int kr = b_kr0 + i * 8;
            cp_async16(&b[kr * 136 + b_nn], g_projr + (size_t)(k0 + kr) * RANK + b_nn);
        }
        CP_COMMIT();
    };

    ldg_a(0, rcur0, rcur1);
    cp_b(0);

    for (int c = 0; c < S1_CHUNKS; c++) {
        const bool more = (c + 1 < S1_CHUNKS);
        if (more) {
            ldg_a(c + 1, rnx0, rnx1);      // issue next-chunk LDGs early
            cp_b(c + 1);
        }
        sts_a(rcur0, rcur1, c & 1);
        if (more) { CP_WAIT(1); } else { CP_WAIT(0); }
        __syncthreads();

        const float* a = sA + (c & 1) * S1_AS;
        const float* b = sB + (c & 1) * S1_BS;
#pragma unroll
        for (int ks = 0; ks < 4; ks++) {
            const int kb = ks * 8;
            unsigned af[2][4];
#pragma unroll
            for (int mt = 0; mt < 2; mt++) {
                int row = wm * 32 + mt * 16;
                af[mt][0] = __float_as_uint(a[(row + g    ) * 36 + kb + tg    ]);
                af[mt][1] = __float_as_uint(a[(row + g + 8) * 36 + kb + tg    ]);
                af[mt][2] = __float_as_uint(a[(row + g    ) * 36 + kb + tg + 4]);
                af[mt][3] = __float_as_uint(a[(row + g + 8) * 36 + kb + tg + 4]);
            }
            unsigned bf[4][2];
#pragma unroll
            for (int nt = 0; nt < 4; nt++) {
                int col = wn * 32 + nt * 8 + g;
                bf[nt][0] = __float_as_uint(b[(kb + tg    ) * 136 + col]);
                bf[nt][1] = __float_as_uint(b[(kb + tg + 4) * 136 + col]);
            }
#pragma unroll
            for (int mt = 0; mt < 2; mt++)
#pragma unroll
                for (int nt = 0; nt < 4; nt++)
                    mma_tf32(acc[mt][nt][0], acc[mt][nt][1], acc[mt][nt][2], acc[mt][nt][3],
                             af[mt][0], af[mt][1], af[mt][2], af[mt][3],
                             bf[nt][0], bf[nt][1]);
        }
        __syncthreads();   // protects both smem buffers for next-iteration writes

        rcur0 = rnx0; rcur1 = rnx1;
    }

    // epilogue: round t to tf32 and store
#pragma unroll
    for (int mt = 0; mt < 2; mt++) {
#pragma unroll
        for (int nt = 0; nt < 4; nt++) {
            int row = m0 + wm * 32 + mt * 16 + g;
            int col = wn * 32 + nt * 8 + tg * 2;
            float2 lo, hi;
            lo.x = __uint_as_float(tf32r(acc[mt][nt][0]));
            lo.y = __uint_as_float(tf32r(acc[mt][nt][1]));
            hi.x = __uint_as_float(tf32r(acc[mt][nt][2]));
            hi.y = __uint_as_float(tf32r(acc[mt][nt][3]));
            *(float2*)(&g_t[(size_t)row * RANK + col])       = lo;
            *(float2*)(&g_t[(size_t)(row + 8) * RANK + col]) = hi;
        }
    }
}

// ---------------------------------------------------------------------------
// Kernel 2: row norms of t (from the tf32-rounded values). One warp per row.
// ---------------------------------------------------------------------------
__global__ __launch_bounds__(256) void norms_kernel() {
    int row  = blockIdx.x * 8 + (threadIdx.x >> 5);
    int lane = threadIdx.x & 31;
    float4 v = *(const float4*)(g_t + (size_t)row * RANK + lane * 4);
    float s = v.x * v.x + v.y * v.y + v.z * v.z + v.w * v.w;
#pragma unroll
    for (int off = 16; off > 0; off >>= 1)
        s += __shfl_xor_sync(0xFFFFFFFFu, s, off);
    if (lane == 0) g_norms[row] = s;
}

// ---------------------------------------------------------------------------
// Kernel 3: out[b,i,j] = max(n_i + n_j - 2 * t_i . t_j, 0)
// Per-batch 1024x1024x128. CTA tile 128x128, K-chunk 32, 2-stage cp.async.
// 8 warps = 4(m) x 2(n); warp tile 32x64. t is already exact tf32.
// ---------------------------------------------------------------------------
#define S2_TS (128 * 36)
#define S2_CHUNKS (RANK / 32)

__global__ __launch_bounds__(256, 2) void gemm2_kernel(float* __restrict__ out) {
    extern __shared__ float smem[];
    float* sA = smem;                 // [2][128][36]
    float* sB = smem + 2 * S2_TS;     // [2][128][36]
    __shared__ float nI[128], nJ[128];

    const int tid  = threadIdx.x;
    const int warp = tid >> 5, lane = tid & 31;
    const int wm = warp >> 1, wn = warp & 1;
    const int g  = lane >> 2, tg = lane & 3;

    const int b  = blockIdx.z;
    const int bi = blockIdx.y;
    const int bj = blockIdx.x;

    const float* tb = g_t + (size_t)b * SEQ * RANK;

    if (tid < 128)       nI[tid]       = g_norms[b * SEQ + bi * 128 + tid];
    else                 nJ[tid - 128] = g_norms[b * SEQ + bj * 128 + (tid - 128)];

    float acc[2][8][4];
#pragma unroll
    for (int mt = 0; mt < 2; mt++)
#pragma unroll
        for (int nt = 0; nt < 8; nt++)
#pragma unroll
            for (int v = 0; v < 4; v++) acc[mt][nt][v] = 0.0f;

    const int l_row0 = tid >> 3, l_kk = (tid & 7) * 4;

    auto load_chunk = [&](int c) {
        const int s  = c & 1;
        const int k0 = c * 32;
        float* a  = sA + s * S2_TS;
        float* bb = sB + s * S2_TS;
#pragma unroll
        for (int i = 0; i < 4; i++) {
            int row = l_row0 + i * 32;
            cp_async16(&a[row * 36 + l_kk],
                       tb + (size_t)(bi * 128 + row) * RANK + k0 + l_kk);
            cp_async16(&bb[row * 36 + l_kk],
                       tb + (size_t)(bj * 128 + row) * RANK + k0 + l_kk);
        }
        CP_COMMIT();
    };

    load_chunk(0);

#pragma unroll
    for (int c = 0; c < S2_CHUNKS; c++) {
        if (c + 1 < S2_CHUNKS) { load_chunk(c + 1); CP_WAIT(1); } else { CP_WAIT(0); }
        __syncthreads();

        const int s = c & 1;
        const float* a  = sA + s * S2_TS;
        const float* bb = sB + s * S2_TS;
#pragma unroll
        for (int ks = 0; ks < 4; ks++) {
            const int kb = ks * 8;
            unsigned af[2][4];
#pragma unroll
            for (int mt = 0; mt < 2; mt++) {
                int row = wm * 32 + mt * 16;
                af[mt][0] = __float_as_uint(a[(row + g    ) * 36 + kb + tg    ]);
                af[mt][1] = __float_as_uint(a[(row + g + 8) * 36 + kb + tg    ]);
                af[mt][2] = __float_as_uint(a[(row + g    ) * 36 + kb + tg + 4]);
                af[mt][3] = __float_as_uint(a[(row + g + 8) * 36 + kb + tg + 4]);
            }
            unsigned bf[8][2];
#pragma unroll
            for (int nt = 0; nt < 8; nt++) {
                int col = wn * 64 + nt * 8 + g;
                bf[nt][0] = __float_as_uint(bb[col * 36 + kb + tg    ]);
                bf[nt][1] = __float_as_uint(bb[col * 36 + kb + tg + 4]);
            }
#pragma unroll
            for (int mt = 0; mt < 2; mt++)
#pragma unroll
                for (int nt = 0; nt < 8; nt++)
                    mma_tf32(acc[mt][nt][0], acc[mt][nt][1], acc[mt][nt][2], acc[mt][nt][3],
                             af[mt][0], af[mt][1], af[mt][2], af[mt][3],
                             bf[nt][0], bf[nt][1]);
        }
        __syncthreads();
    }

    float* outb = out + (size_t)b * SEQ * SEQ;
#pragma unroll
    for (int mt = 0; mt < 2; mt++) {
#pragma unroll
        for (int nt = 0; nt < 8; nt++) {
            int r0 = wm * 32 + mt * 16 + g;
            int c  = wn * 64 + nt * 8 + tg * 2;
            float ni0 = nI[r0], ni1 = nI[r0 + 8];
            float nj0 = nJ[c],  nj1 = nJ[c + 1];
            float2 lo, hi;
            lo.x = fmaxf(ni0 + nj0 - 2.0f * acc[mt][nt][0], 0.0f);
            lo.y = fmaxf(ni0 + nj1 - 2.0f * acc[mt][nt][1], 0.0f);
            hi.x = fmaxf(ni1 + nj0 - 2.0f * acc[mt][nt][2], 0.0f);
            hi.y = fmaxf(ni1 + nj1 - 2.0f * acc[mt][nt][3], 0.0f);
            size_t base = (size_t)(bi * 128 + r0) * SEQ + bj * 128 + c;
            *(float2*)(&outb[base])                   = lo;
            *(float2*)(&outb[base + (size_t)8 * SEQ]) = hi;
        }
    }
}

// ---------------------------------------------------------------------------
extern "C" void kernel_launch(void* const* d_in, const int* in_sizes, int n_in,
                              void* d_out, int out_size) {
    const float* batch = (const float*)d_in[0];   // [16,1024,1024] f32
    const float* proj  = (const float*)d_in[1];   // [1024,128] f32
    float* out = (float*)d_out;                   // [16,1024,1024] f32
    (void)in_sizes; (void)n_in; (void)out_size;

    static const size_t s1_smem = (size_t)2 * (S1_AS + S1_BS) * sizeof(float);  // 53.25 KB
    static const size_t s2_smem = (size_t)4 * S2_TS * sizeof(float);            // 73.7 KB

    cudaFuncSetAttribute(gemm1_kernel, cudaFuncAttributeMaxDynamicSharedMemorySize, (int)s1_smem);
    cudaFuncSetAttribute(gemm2_kernel, cudaFuncAttributeMaxDynamicSharedMemorySize, (int)s2_smem);

    round_proj_kernel<<<DIM * RANK / 4 / 256, 256>>>(proj);
    gemm1_kernel<<<SEQ * BATCH / 64, 256, s1_smem>>>(batch);
    norms_kernel<<<BATCH * SEQ / 8, 256>>>();
    gemm2_kernel<<<dim3(8, 8, BATCH), 256, s2_smem>>>(out);
}

// round 8
// speedup vs baseline: 1.7347x; 1.0856x over previous
#include <cuda_runtime.h>
#include <cstdint>

// ---------------------------------------------------------------------------
// TwoWordPSDProbe: out[b,i,j] = max(||t_i||^2 + ||t_j||^2 - 2 t_i.t_j, 0)
// where t = batch @ proj.  B=16, S=1024, D=1024, R=128.
//
// tf32 mma.sync both GEMMs, 3-stage single-barrier pipelines.
// gemm1 inputs explicitly rounded (cvt.rna) - HW truncation is biased.
// gemm2 computes only the upper triangle of (bi,bj) tile pairs and mirrors
// the off-diagonal tiles through an smem transpose.
// ---------------------------------------------------------------------------

#define BATCH 16
#define SEQ   1024
#define DIM   1024
#define RANK  128

static __device__ __align__(16) float g_t[BATCH * SEQ * RANK];      // 8 MB
static __device__ __align__(16) float g_projr[DIM * RANK];           // 512 KB
static __device__ float g_norms[BATCH * SEQ];                        // 64 KB

// upper-triangle tile-pair LUT (8x8 tiles -> 36 pairs)
__constant__ int c_pi[36] = {0,0,0,0,0,0,0,0, 1,1,1,1,1,1,1, 2,2,2,2,2,2,
                             3,3,3,3,3, 4,4,4,4, 5,5,5, 6,6, 7};
__constant__ int c_pj[36] = {0,1,2,3,4,5,6,7, 1,2,3,4,5,6,7, 2,3,4,5,6,7,
                             3,4,5,6,7, 4,5,6,7, 5,6,7, 6,7, 7};

__device__ __forceinline__ unsigned tf32r(float x) {
    unsigned y;
    asm("cvt.rna.tf32.f32 %0, %1;" : "=r"(y) : "f"(x));
    return y;
}

__device__ __forceinline__ void mma_tf32(float& d0, float& d1, float& d2, float& d3,
                                         unsigned a0, unsigned a1, unsigned a2, unsigned a3,
                                         unsigned b0, unsigned b1) {
    asm volatile(
        "mma.sync.aligned.m16n8k8.row.col.f32.tf32.tf32.f32 "
        "{%0,%1,%2,%3}, {%4,%5,%6,%7}, {%8,%9}, {%0,%1,%2,%3};"
        : "+f"(d0), "+f"(d1), "+f"(d2), "+f"(d3)
        : "r"(a0), "r"(a1), "r"(a2), "r"(a3), "r"(b0), "r"(b1));
}

__device__ __forceinline__ void cp_async16(void* sptr, const void* gptr) {
    unsigned saddr = (unsigned)__cvta_generic_to_shared(sptr);
    asm volatile("cp.async.cg.shared.global [%0], [%1], 16;\n" :: "r"(saddr), "l"(gptr));
}
#define CP_COMMIT() asm volatile("cp.async.commit_group;\n")
#define CP_WAIT(N)  asm volatile("cp.async.wait_group %0;\n" :: "n"(N))

// ---------------------------------------------------------------------------
// Kernel 0: round proj to tf32 once.
// ---------------------------------------------------------------------------
__global__ __launch_bounds__(256) void round_proj_kernel(const float* __restrict__ proj) {
    int i = blockIdx.x * 256 + threadIdx.x;
    float4 v = ((const float4*)proj)[i];
    v.x = __uint_as_float(tf32r(v.x));
    v.y = __uint_as_float(tf32r(v.y));
    v.z = __uint_as_float(tf32r(v.z));
    v.w = __uint_as_float(tf32r(v.w));
    ((float4*)g_projr)[i] = v;
}

// ---------------------------------------------------------------------------
// Kernel 1: t = batch @ proj   (M=16384, N=128, K=1024)
// CTA 64x128, grid 256, 8 warps = 2(m) x 4(n), warp 32x32. K-chunk 32.
// 3-stage ring, ONE barrier per chunk: iter c fills buf (c+1)%3, MMAs buf c%3.
// A: LDG (1 chunk ahead) -> cvt.rna -> STS.  B: cp.async from g_projr.
// ---------------------------------------------------------------------------
#define S1_AS (64 * 36)
#define S1_BS (32 * 136)
#define S1_CHUNKS (DIM / 32)

__global__ __launch_bounds__(256, 2) void gemm1_kernel(const float* __restrict__ batch) {
    extern __shared__ float smem[];
    float* sA = smem;               // [3][64][36]
    float* sB = smem + 3 * S1_AS;   // [3][32][136]

    const int tid  = threadIdx.x;
    const int warp = tid >> 5, lane = tid & 31;
    const int wm = warp >> 2, wn = warp & 3;
    const int g  = lane >> 2, tg = lane & 3;
    const int m0 = blockIdx.x * 64;

    float acc[2][4][4];
#pragma unroll
    for (int mt = 0; mt < 2; mt++)
#pragma unroll
        for (int nt = 0; nt < 4; nt++)
#pragma unroll
            for (int v = 0; v < 4; v++) acc[mt][nt][v] = 0.0f;

    const int a_row0 = tid >> 3, a_kk = (tid & 7) * 4;
    const int b_kr0  = tid >> 5, b_nn = lane * 4;

    const float* aptr0 = batch + (size_t)(m0 + a_row0) * DIM + a_kk;
    const float* aptr1 = batch + (size_t)(m0 + a_row0 + 32) * DIM + a_kk;

    float4 rcur0, rcur1, rnx0, rnx1;

    auto ldg_a = [&](int c, float4& r0, float4& r1) {
        r0 = *(const float4*)(aptr0 + c * 32);
        r1 = *(const float4*)(aptr1 + c * 32);
    };
    auto sts_a = [&](const float4& r0, const float4& r1, int s) {
        float* a = sA + s * S1_AS;
        float4 v0, v1;
        v0.x = __uint_as_float(tf32r(r0.x)); v0.y = __uint_as_float(tf32r(r0.y));
        v0.z = __uint_as_float(tf32r(r0.z)); v0.w = __uint_as_float(tf32r(r0.w));
        v1.x = __uint_as_float(tf32r(r1.x)); v1.y = __uint_as_float(tf32r(r1.y));
        v1.z = __uint_as_float(tf32r(r1.z)); v1.w = __uint_as_float(tf32r(r1.w));
        *(float4*)(&a[a_row0 * 36 + a_kk])        = v0;
        *(float4*)(&a[(a_row0 + 32) * 36 + a_kk]) = v1;
    };
    auto cp_b = [&](int c, int s) {
        float* b = sB + s * S1_BS;
        const int k0 = c * 32;
#pragma unroll
        for (int i = 0; i < 4; i++) {
            int kr = b_kr0 + i * 8;
            cp_async16(&b[kr * 136 + b_nn], g_projr + (size_t)(k0 + kr) * RANK + b_nn);
        }
        CP_COMMIT();
    };

    // prologue: chunk0 -> buf0; prefetch chunk1 into regs
    ldg_a(0, rcur0, rcur1);
    sts_a(rcur0, rcur1, 0);
    cp_b(0, 0);
    ldg_a(1, rcur0, rcur1);

    for (int c = 0; c < S1_CHUNKS; c++) {
        // fill buffer (c+1)%3 with chunk c+1; prefetch chunk c+2
        if (c + 1 < S1_CHUNKS) {
            sts_a(rcur0, rcur1, (c + 1) % 3);
            cp_b(c + 1, (c + 1) % 3);
            if (c + 2 < S1_CHUNKS) ldg_a(c + 2, rnx0, rnx1);
            CP_WAIT(1);
        } else {
            CP_WAIT(0);
        }
        __syncthreads();

        const float* a = sA + (c % 3) * S1_AS;
        const float* b = sB + (c % 3) * S1_BS;
#pragma unroll
        for (int ks = 0; ks < 4; ks++) {
            const int kb = ks * 8;
            unsigned af[2][4];
#pragma unroll
            for (int mt = 0; mt < 2; mt++) {
                int row = wm * 32 + mt * 16;
                af[mt][0] = __float_as_uint(a[(row + g    ) * 36 + kb + tg    ]);
                af[mt][1] = __float_as_uint(a[(row + g + 8) * 36 + kb + tg    ]);
                af[mt][2] = __float_as_uint(a[(row + g    ) * 36 + kb + tg + 4]);
                af[mt][3] = __float_as_uint(a[(row + g + 8) * 36 + kb + tg + 4]);
            }
            unsigned bf[4][2];
#pragma unroll
            for (int nt = 0; nt < 4; nt++) {
                int col = wn * 32 + nt * 8 + g;
                bf[nt][0] = __float_as_uint(b[(kb + tg    ) * 136 + col]);
                bf[nt][1] = __float_as_uint(b[(kb + tg + 4) * 136 + col]);
            }
#pragma unroll
            for (int mt = 0; mt < 2; mt++)
#pragma unroll
                for (int nt = 0; nt < 4; nt++)
                    mma_tf32(acc[mt][nt][0], acc[mt][nt][1], acc[mt][nt][2], acc[mt][nt][3],
                             af[mt][0], af[mt][1], af[mt][2], af[mt][3],
                             bf[nt][0], bf[nt][1]);
        }
        rcur0 = rnx0; rcur1 = rnx1;
    }

    // epilogue: round t to tf32 and store
#pragma unroll
    for (int mt = 0; mt < 2; mt++) {
#pragma unroll
        for (int nt = 0; nt < 4; nt++) {
            int row = m0 + wm * 32 + mt * 16 + g;
            int col = wn * 32 + nt * 8 + tg * 2;
            float2 lo, hi;
            lo.x = __uint_as_float(tf32r(acc[mt][nt][0]));
            lo.y = __uint_as_float(tf32r(acc[mt][nt][1]));
            hi.x = __uint_as_float(tf32r(acc[mt][nt][2]));
            hi.y = __uint_as_float(tf32r(acc[mt][nt][3]));
            *(float2*)(&g_t[(size_t)row * RANK + col])       = lo;
            *(float2*)(&g_t[(size_t)(row + 8) * RANK + col]) = hi;
        }
    }
}

// ---------------------------------------------------------------------------
// Kernel 2: row norms of t. One warp per row.
// ---------------------------------------------------------------------------
__global__ __launch_bounds__(256) void norms_kernel() {
    int row  = blockIdx.x * 8 + (threadIdx.x >> 5);
    int lane = threadIdx.x & 31;
    float4 v = *(const float4*)(g_t + (size_t)row * RANK + lane * 4);
    float s = v.x * v.x + v.y * v.y + v.z * v.z + v.w * v.w;
#pragma unroll
    for (int off = 16; off > 0; off >>= 1)
        s += __shfl_xor_sync(0xFFFFFFFFu, s, off);
    if (lane == 0) g_norms[row] = s;
}

// ---------------------------------------------------------------------------
// Kernel 3: upper-triangle tile pairs only; mirror off-diagonal via smem
// transpose. CTA tile 128x128, K-chunk 32, 3-stage ring, one barrier/chunk.
// 8 warps = 4(m) x 2(n); warp tile 32x64.
// ---------------------------------------------------------------------------
#define S2_TS (128 * 36)
#define S2_CHUNKS (RANK / 32)

__global__ __launch_bounds__(256, 2) void gemm2_kernel(float* __restrict__ out) {
    extern __shared__ float smem[];
    float* sA = smem;                 // [3][128][36]
    float* sB = smem + 3 * S2_TS;     // [3][128][36]
    __shared__ float nI[128], nJ[128];

    const int tid  = threadIdx.x;
    const int warp = tid >> 5, lane = tid & 31;
    const int wm = warp >> 1, wn = warp & 1;
    const int g  = lane >> 2, tg = lane & 3;

    const int b  = blockIdx.y;
    const int bi = c_pi[blockIdx.x];
    const int bj = c_pj[blockIdx.x];

    const float* tb = g_t + (size_t)b * SEQ * RANK;

    if (tid < 128)       nI[tid]       = g_norms[b * SEQ + bi * 128 + tid];
    else                 nJ[tid - 128] = g_norms[b * SEQ + bj * 128 + (tid - 128)];

    float acc[2][8][4];
#pragma unroll
    for (int mt = 0; mt < 2; mt++)
#pragma unroll
        for (int nt = 0; nt < 8; nt++)
#pragma unroll
            for (int v = 0; v < 4; v++) acc[mt][nt][v] = 0.0f;

    const int l_row0 = tid >> 3, l_kk = (tid & 7) * 4;

    auto load_chunk = [&](int c, int s) {
        const int k0 = c * 32;
        float* a  = sA + s * S2_TS;
        float* bb = sB + s * S2_TS;
#pragma unroll
        for (int i = 0; i < 4; i++) {
            int row = l_row0 + i * 32;
            cp_async16(&a[row * 36 + l_kk],
                       tb + (size_t)(bi * 128 + row) * RANK + k0 + l_kk);
            cp_async16(&bb[row * 36 + l_kk],
                       tb + (size_t)(bj * 128 + row) * RANK + k0 + l_kk);
        }
        CP_COMMIT();
    };

    load_chunk(0, 0);

#pragma unroll
    for (int c = 0; c < S2_CHUNKS; c++) {
        if (c + 1 < S2_CHUNKS) { load_chunk(c + 1, (c + 1) % 3); CP_WAIT(1); }
        else                   { CP_WAIT(0); }
        __syncthreads();

        const float* a  = sA + (c % 3) * S2_TS;
        const float* bb = sB + (c % 3) * S2_TS;
#pragma unroll
        for (int ks = 0; ks < 4; ks++) {
            const int kb = ks * 8;
            unsigned af[2][4];
#pragma unroll
            for (int mt = 0; mt < 2; mt++) {
                int row = wm * 32 + mt * 16;
                af[mt][0] = __float_as_uint(a[(row + g    ) * 36 + kb + tg    ]);
                af[mt][1] = __float_as_uint(a[(row + g + 8) * 36 + kb + tg    ]);
                af[mt][2] = __float_as_uint(a[(row + g    ) * 36 + kb + tg + 4]);
                af[mt][3] = __float_as_uint(a[(row + g + 8) * 36 + kb + tg + 4]);
            }
            unsigned bf[8][2];
#pragma unroll
            for (int nt = 0; nt < 8; nt++) {
                int col = wn * 64 + nt * 8 + g;
                bf[nt][0] = __float_as_uint(bb[col * 36 + kb + tg    ]);
                bf[nt][1] = __float_as_uint(bb[col * 36 + kb + tg + 4]);
            }
#pragma unroll
            for (int mt = 0; mt < 2; mt++)
#pragma unroll
                for (int nt = 0; nt < 8; nt++)
                    mma_tf32(acc[mt][nt][0], acc[mt][nt][1], acc[mt][nt][2], acc[mt][nt][3],
                             af[mt][0], af[mt][1], af[mt][2], af[mt][3],
                             bf[nt][0], bf[nt][1]);
        }
    }

    // epilogue: finalize values in-place, direct store to (bi,bj)
    float* outb = out + (size_t)b * SEQ * SEQ;
#pragma unroll
    for (int mt = 0; mt < 2; mt++) {
#pragma unroll
        for (int nt = 0; nt < 8; nt++) {
            int r0 = wm * 32 + mt * 16 + g;
            int c  = wn * 64 + nt * 8 + tg * 2;
            float ni0 = nI[r0], ni1 = nI[r0 + 8];
            float nj0 = nJ[c],  nj1 = nJ[c + 1];
            acc[mt][nt][0] = fmaxf(ni0 + nj0 - 2.0f * acc[mt][nt][0], 0.0f);
            acc[mt][nt][1] = fmaxf(ni0 + nj1 - 2.0f * acc[mt][nt][1], 0.0f);
            acc[mt][nt][2] = fmaxf(ni1 + nj0 - 2.0f * acc[mt][nt][2], 0.0f);
            acc[mt][nt][3] = fmaxf(ni1 + nj1 - 2.0f * acc[mt][nt][3], 0.0f);
            size_t base = (size_t)(bi * 128 + r0) * SEQ + bj * 128 + c;
            *(float2*)(&outb[base])                   = make_float2(acc[mt][nt][0], acc[mt][nt][1]);
            *(float2*)(&outb[base + (size_t)8 * SEQ]) = make_float2(acc[mt][nt][2], acc[mt][nt][3]);
        }
    }

    // mirror tile (bj,bi) via smem transpose (pad 129 -> conflict-free)
    if (bi != bj) {
        __syncthreads();          // MMA/loop smem dead; safe to reuse
        float* sT = smem;         // 128*129 floats = 66 KB (< 3*S2_TS*2)
#pragma unroll
        for (int mt = 0; mt < 2; mt++) {
#pragma unroll
            for (int nt = 0; nt < 8; nt++) {
                int r0 = wm * 32 + mt * 16 + g;
                int c  = wn * 64 + nt * 8 + tg * 2;
                sT[r0 * 129 + c]           = acc[mt][nt][0];
                sT[r0 * 129 + c + 1]       = acc[mt][nt][1];
                sT[(r0 + 8) * 129 + c]     = acc[mt][nt][2];
                sT[(r0 + 8) * 129 + c + 1] = acc[mt][nt][3];
            }
        }
        __syncthreads();
        const int colw = tid & 127, rsel = tid >> 7;
#pragma unroll 8
        for (int s = 0; s < 64; s++) {
            int row = s * 2 + rsel;
            outb[(size_t)(bj * 128 + row) * SEQ + bi * 128 + colw] = sT[colw * 129 + row];
        }
    }
}

// ---------------------------------------------------------------------------
extern "C" void kernel_launch(void* const* d_in, const int* in_sizes, int n_in,
                              void* d_out, int out_size) {
    const float* batch = (const float*)d_in[0];   // [16,1024,1024] f32
    const float* proj  = (const float*)d_in[1];   // [1024,128] f32
    float* out = (float*)d_out;                   // [16,1024,1024] f32
    (void)in_sizes; (void)n_in; (void)out_size;

    static const size_t s1_smem = (size_t)3 * (S1_AS + S1_BS) * sizeof(float);  // 79.9 KB
    static const size_t s2_smem = (size_t)6 * S2_TS * sizeof(float);            // 110.6 KB

    cudaFuncSetAttribute(gemm1_kernel, cudaFuncAttributeMaxDynamicSharedMemorySize, (int)s1_smem);
    cudaFuncSetAttribute(gemm2_kernel, cudaFuncAttributeMaxDynamicSharedMemorySize, (int)s2_smem);

    round_proj_kernel<<<DIM * RANK / 4 / 256, 256>>>(proj);
    gemm1_kernel<<<SEQ * BATCH / 64, 256, s1_smem>>>(batch);
    norms_kernel<<<BATCH * SEQ / 8, 256>>>();
    gemm2_kernel<<<dim3(36, BATCH), 256, s2_smem>>>(out);
}

// round 9
// speedup vs baseline: 1.7488x; 1.0082x over previous
#include <cuda_runtime.h>
#include <cstdint>

// ---------------------------------------------------------------------------
// TwoWordPSDProbe: out[b,i,j] = max(||t_i||^2 + ||t_j||^2 - 2 t_i.t_j, 0)
// where t = batch @ proj.  B=16, S=1024, D=1024, R=128.
//
// tf32 mma.sync both GEMMs, 3-stage single-barrier pipelines.
// gemm1 inputs explicitly rounded (cvt.rna) - HW truncation is biased.
// gemm2 computes only the upper triangle of (bi,bj) tile pairs and mirrors
// the off-diagonal tiles through an smem transpose.
// ---------------------------------------------------------------------------

#define BATCH 16
#define SEQ   1024
#define DIM   1024
#define RANK  128

static __device__ __align__(16) float g_t[BATCH * SEQ * RANK];      // 8 MB
static __device__ __align__(16) float g_projr[DIM * RANK];           // 512 KB
static __device__ float g_norms[BATCH * SEQ];                        // 64 KB

// upper-triangle tile-pair LUT (8x8 tiles -> 36 pairs)
__constant__ int c_pi[36] = {0,0,0,0,0,0,0,0, 1,1,1,1,1,1,1, 2,2,2,2,2,2,
                             3,3,3,3,3, 4,4,4,4, 5,5,5, 6,6, 7};
__constant__ int c_pj[36] = {0,1,2,3,4,5,6,7, 1,2,3,4,5,6,7, 2,3,4,5,6,7,
                             3,4,5,6,7, 4,5,6,7, 5,6,7, 6,7, 7};

__device__ __forceinline__ unsigned tf32r(float x) {
    unsigned y;
    asm("cvt.rna.tf32.f32 %0, %1;" : "=r"(y) : "f"(x));
    return y;
}

__device__ __forceinline__ void mma_tf32(float& d0, float& d1, float& d2, float& d3,
                                         unsigned a0, unsigned a1, unsigned a2, unsigned a3,
                                         unsigned b0, unsigned b1) {
    asm volatile(
        "mma.sync.aligned.m16n8k8.row.col.f32.tf32.tf32.f32 "
        "{%0,%1,%2,%3}, {%4,%5,%6,%7}, {%8,%9}, {%0,%1,%2,%3};"
        : "+f"(d0), "+f"(d1), "+f"(d2), "+f"(d3)
        : "r"(a0), "r"(a1), "r"(a2), "r"(a3), "r"(b0), "r"(b1));
}

__device__ __forceinline__ void cp_async16(void* sptr, const void* gptr) {
    unsigned saddr = (unsigned)__cvta_generic_to_shared(sptr);
    asm volatile("cp.async.cg.shared.global [%0], [%1], 16;\n" :: "r"(saddr), "l"(gptr));
}
#define CP_COMMIT() asm volatile("cp.async.commit_group;\n")
#define CP_WAIT(N)  asm volatile("cp.async.wait_group %0;\n" :: "n"(N))

// ---------------------------------------------------------------------------
// Kernel 0: round proj to tf32 once.
// ---------------------------------------------------------------------------
__global__ __launch_bounds__(256) void round_proj_kernel(const float* __restrict__ proj) {
    int i = blockIdx.x * 256 + threadIdx.x;
    float4 v = ((const float4*)proj)[i];
    v.x = __uint_as_float(tf32r(v.x));
    v.y = __uint_as_float(tf32r(v.y));
    v.z = __uint_as_float(tf32r(v.z));
    v.w = __uint_as_float(tf32r(v.w));
    ((float4*)g_projr)[i] = v;
}

// ---------------------------------------------------------------------------
// Kernel 1: t = batch @ proj   (M=16384, N=128, K=1024)
// CTA 64x128, grid 256, 8 warps = 2(m) x 4(n), warp 32x32. K-chunk 32.
// 3-stage ring, ONE barrier per chunk: iter c fills buf (c+1)%3, MMAs buf c%3.
// A: LDG (1 chunk ahead) -> cvt.rna -> STS.  B: cp.async from g_projr.
// ---------------------------------------------------------------------------
#define S1_AS (64 * 36)
#define S1_BS (32 * 136)
#define S1_CHUNKS (DIM / 32)

__global__ __launch_bounds__(256, 2) void gemm1_kernel(const float* __restrict__ batch) {
    extern __shared__ float smem[];
    float* sA = smem;               // [3][64][36]
    float* sB = smem + 3 * S1_AS;   // [3][32][136]

    const int tid  = threadIdx.x;
    const int warp = tid >> 5, lane = tid & 31;
    const int wm = warp >> 2, wn = warp & 3;
    const int g  = lane >> 2, tg = lane & 3;
    const int m0 = blockIdx.x * 64;

    float acc[2][4][4];
#pragma unroll
    for (int mt = 0; mt < 2; mt++)
#pragma unroll
        for (int nt = 0; nt < 4; nt++)
#pragma unroll
            for (int v = 0; v < 4; v++) acc[mt][nt][v] = 0.0f;

    const int a_row0 = tid >> 3, a_kk = (tid & 7) * 4;
    const int b_kr0  = tid >> 5, b_nn = lane * 4;

    const float* aptr0 = batch + (size_t)(m0 + a_row0) * DIM + a_kk;
    const float* aptr1 = batch + (size_t)(m0 + a_row0 + 32) * DIM + a_kk;

    float4 rcur0, rcur1, rnx0, rnx1;

    auto ldg_a = [&](int c, float4& r0, float4& r1) {
        r0 = *(const float4*)(aptr0 + c * 32);
        r1 = *(const float4*)(aptr1 + c * 32);
    };
    auto sts_a = [&](const float4& r0, const float4& r1, int s) {
        float* a = sA + s * S1_AS;
        float4 v0, v1;
        v0.x = __uint_as_float(tf32r(r0.x)); v0.y = __uint_as_float(tf32r(r0.y));
        v0.z = __uint_as_float(tf32r(r0.z)); v0.w = __uint_as_float(tf32r(r0.w));
        v1.x = __uint_as_float(tf32r(r1.x)); v1.y = __uint_as_float(tf32r(r1.y));
        v1.z = __uint_as_float(tf32r(r1.z)); v1.w = __uint_as_float(tf32r(r1.w));
        *(float4*)(&a[a_row0 * 36 + a_kk])        = v0;
        *(float4*)(&a[(a_row0 + 32) * 36 + a_kk]) = v1;
    };
    auto cp_b = [&](int c, int s) {
        float* b = sB + s * S1_BS;
        const int k0 = c * 32;
#pragma unroll
        for (int i = 0; i < 4; i++) {
            int kr = b_kr0 + i * 8;
            cp_async16(&b[kr * 136 + b_nn], g_projr + (size_t)(k0 + kr) * RANK + b_nn);
        }
        CP_COMMIT();
    };

    // prologue: chunk0 -> buf0; prefetch chunk1 into regs
    ldg_a(0, rcur0, rcur1);
    sts_a(rcur0, rcur1, 0);
    cp_b(0, 0);
    ldg_a(1, rcur0, rcur1);

    for (int c = 0; c < S1_CHUNKS; c++) {
        // fill buffer (c+1)%3 with chunk c+1; prefetch chunk c+2
        if (c + 1 < S1_CHUNKS) {
            sts_a(rcur0, rcur1, (c + 1) % 3);
            cp_b(c + 1, (c + 1) % 3);
            if (c + 2 < S1_CHUNKS) ldg_a(c + 2, rnx0, rnx1);
            CP_WAIT(1);
        } else {
            CP_WAIT(0);
        }
        __syncthreads();

        const float* a = sA + (c % 3) * S1_AS;
        const float* b = sB + (c % 3) * S1_BS;
#pragma unroll
        for (int ks = 0; ks < 4; ks++) {
            const int kb = ks * 8;
            unsigned af[2][4];
#pragma unroll
            for (int mt = 0; mt < 2; mt++) {
                int row = wm * 32 + mt * 16;
                af[mt][0] = __float_as_uint(a[(row + g    ) * 36 + kb + tg    ]);
                af[mt][1] = __float_as_uint(a[(row + g + 8) * 36 + kb + tg    ]);
                af[mt][2] = __float_as_uint(a[(row + g    ) * 36 + kb + tg + 4]);
                af[mt][3] = __float_as_uint(a[(row + g + 8) * 36 + kb + tg + 4]);
            }
            unsigned bf[4][2];
#pragma unroll
            for (int nt = 0; nt < 4; nt++) {
                int col = wn * 32 + nt * 8 + g;
                bf[nt][0] = __float_as_uint(b[(kb + tg    ) * 136 + col]);
                bf[nt][1] = __float_as_uint(b[(kb + tg + 4) * 136 + col]);
            }
#pragma unroll
            for (int mt = 0; mt < 2; mt++)
#pragma unroll
                for (int nt = 0; nt < 4; nt++)
                    mma_tf32(acc[mt][nt][0], acc[mt][nt][1], acc[mt][nt][2], acc[mt][nt][3],
                             af[mt][0], af[mt][1], af[mt][2], af[mt][3],
                             bf[nt][0], bf[nt][1]);
        }
        rcur0 = rnx0; rcur1 = rnx1;
    }

    // epilogue: round t to tf32 and store
#pragma unroll
    for (int mt = 0; mt < 2; mt++) {
#pragma unroll
        for (int nt = 0; nt < 4; nt++) {
            int row = m0 + wm * 32 + mt * 16 + g;
            int col = wn * 32 + nt * 8 + tg * 2;
            float2 lo, hi;
            lo.x = __uint_as_float(tf32r(acc[mt][nt][0]));
            lo.y = __uint_as_float(tf32r(acc[mt][nt][1]));
            hi.x = __uint_as_float(tf32r(acc[mt][nt][2]));
            hi.y = __uint_as_float(tf32r(acc[mt][nt][3]));
            *(float2*)(&g_t[(size_t)row * RANK + col])       = lo;
            *(float2*)(&g_t[(size_t)(row + 8) * RANK + col]) = hi;
        }
    }
}

// ---------------------------------------------------------------------------
// Kernel 2: row norms of t. One warp per row.
// ---------------------------------------------------------------------------
__global__ __launch_bounds__(256) void norms_kernel() {
    int row  = blockIdx.x * 8 + (threadIdx.x >> 5);
    int lane = threadIdx.x & 31;
    float4 v = *(const float4*)(g_t + (size_t)row * RANK + lane * 4);
    float s = v.x * v.x + v.y * v.y + v.z * v.z + v.w * v.w;
#pragma unroll
    for (int off = 16; off > 0; off >>= 1)
        s += __shfl_xor_sync(0xFFFFFFFFu, s, off);
    if (lane == 0) g_norms[row] = s;
}

// ---------------------------------------------------------------------------
// Kernel 3: upper-triangle tile pairs only; mirror off-diagonal via smem
// transpose. CTA tile 128x128, K-chunk 32, 3-stage ring, one barrier/chunk.
// 8 warps = 4(m) x 2(n); warp tile 32x64.
// ---------------------------------------------------------------------------
#define S2_TS (128 * 36)
#define S2_CHUNKS (RANK / 32)

__global__ __launch_bounds__(256, 2) void gemm2_kernel(float* __restrict__ out) {
    extern __shared__ float smem[];
    float* sA = smem;                 // [3][128][36]
    float* sB = smem + 3 * S2_TS;     // [3][128][36]
    __shared__ float nI[128], nJ[128];

    const int tid  = threadIdx.x;
    const int warp = tid >> 5, lane = tid & 31;
    const int wm = warp >> 1, wn = warp & 1;
    const int g  = lane >> 2, tg = lane & 3;

    const int b  = blockIdx.y;
    const int bi = c_pi[blockIdx.x];
    const int bj = c_pj[blockIdx.x];

    const float* tb = g_t + (size_t)b * SEQ * RANK;

    if (tid < 128)       nI[tid]       = g_norms[b * SEQ + bi * 128 + tid];
    else                 nJ[tid - 128] = g_norms[b * SEQ + bj * 128 + (tid - 128)];

    float acc[2][8][4];
#pragma unroll
    for (int mt = 0; mt < 2; mt++)
#pragma unroll
        for (int nt = 0; nt < 8; nt++)
#pragma unroll
            for (int v = 0; v < 4; v++) acc[mt][nt][v] = 0.0f;

    const int l_row0 = tid >> 3, l_kk = (tid & 7) * 4;

    auto load_chunk = [&](int c, int s) {
        const int k0 = c * 32;
        float* a  = sA + s * S2_TS;
        float* bb = sB + s * S2_TS;
#pragma unroll
        for (int i = 0; i < 4; i++) {
            int row = l_row0 + i * 32;
            cp_async16(&a[row * 36 + l_kk],
                       tb + (size_t)(bi * 128 + row) * RANK + k0 + l_kk);
            cp_async16(&bb[row * 36 + l_kk],
                       tb + (size_t)(bj * 128 + row) * RANK + k0 + l_kk);
        }
        CP_COMMIT();
    };

    load_chunk(0, 0);

#pragma unroll
    for (int c = 0; c < S2_CHUNKS; c++) {
        if (c + 1 < S2_CHUNKS) { load_chunk(c + 1, (c + 1) % 3); CP_WAIT(1); }
        else                   { CP_WAIT(0); }
        __syncthreads();

        const float* a  = sA + (c % 3) * S2_TS;
        const float* bb = sB + (c % 3) * S2_TS;
#pragma unroll
        for (int ks = 0; ks < 4; ks++) {
            const int kb = ks * 8;
            unsigned af[2][4];
#pragma unroll
            for (int mt = 0; mt < 2; mt++) {
                int row = wm * 32 + mt * 16;
                af[mt][0] = __float_as_uint(a[(row + g    ) * 36 + kb + tg    ]);
                af[mt][1] = __float_as_uint(a[(row + g + 8) * 36 + kb + tg    ]);
                af[mt][2] = __float_as_uint(a[(row + g    ) * 36 + kb + tg + 4]);
                af[mt][3] = __float_as_uint(a[(row + g + 8) * 36 + kb + tg + 4]);
            }
            unsigned bf[8][2];
#pragma unroll
            for (int nt = 0; nt < 8; nt++) {
                int col = wn * 64 + nt * 8 + g;
                bf[nt][0] = __float_as_uint(bb[col * 36 + kb + tg    ]);
                bf[nt][1] = __float_as_uint(bb[col * 36 + kb + tg + 4]);
            }
#pragma unroll
            for (int mt = 0; mt < 2; mt++)
#pragma unroll
                for (int nt = 0; nt < 8; nt++)
                    mma_tf32(acc[mt][nt][0], acc[mt][nt][1], acc[mt][nt][2], acc[mt][nt][3],
                             af[mt][0], af[mt][1], af[mt][2], af[mt][3],
                             bf[nt][0], bf[nt][1]);
        }
    }

    // epilogue: finalize values in-place, direct store to (bi,bj)
    float* outb = out + (size_t)b * SEQ * SEQ;
#pragma unroll
    for (int mt = 0; mt < 2; mt++) {
#pragma unroll
        for (int nt = 0; nt < 8; nt++) {
            int r0 = wm * 32 + mt * 16 + g;
            int c  = wn * 64 + nt * 8 + tg * 2;
            float ni0 = nI[r0], ni1 = nI[r0 + 8];
            float nj0 = nJ[c],  nj1 = nJ[c + 1];
            acc[mt][nt][0] = fmaxf(ni0 + nj0 - 2.0f * acc[mt][nt][0], 0.0f);
            acc[mt][nt][1] = fmaxf(ni0 + nj1 - 2.0f * acc[mt][nt][1], 0.0f);
            acc[mt][nt][2] = fmaxf(ni1 + nj0 - 2.0f * acc[mt][nt][2], 0.0f);
            acc[mt][nt][3] = fmaxf(ni1 + nj1 - 2.0f * acc[mt][nt][3], 0.0f);
            size_t base = (size_t)(bi * 128 + r0) * SEQ + bj * 128 + c;
            *(float2*)(&outb[base])                   = make_float2(acc[mt][nt][0], acc[mt][nt][1]);
            *(float2*)(&outb[base + (size_t)8 * SEQ]) = make_float2(acc[mt][nt][2], acc[mt][nt][3]);
        }
    }

    // mirror tile (bj,bi) via smem transpose (pad 129 -> conflict-free)
    if (bi != bj) {
        __syncthreads();          // MMA/loop smem dead; safe to reuse
        float* sT = smem;         // 128*129 floats = 66 KB (< 3*S2_TS*2)
#pragma unroll
        for (int mt = 0; mt < 2; mt++) {
#pragma unroll
            for (int nt = 0; nt < 8; nt++) {
                int r0 = wm * 32 + mt * 16 + g;
                int c  = wn * 64 + nt * 8 + tg * 2;
                sT[r0 * 129 + c]           = acc[mt][nt][0];
                sT[r0 * 129 + c + 1]       = acc[mt][nt][1];
                sT[(r0 + 8) * 129 + c]     = acc[mt][nt][2];
                sT[(r0 + 8) * 129 + c + 1] = acc[mt][nt][3];
            }
        }
        __syncthreads();
        const int colw = tid & 127, rsel = tid >> 7;
#pragma unroll 8
        for (int s = 0; s < 64; s++) {
            int row = s * 2 + rsel;
            outb[(size_t)(bj * 128 + row) * SEQ + bi * 128 + colw] = sT[colw * 129 + row];
        }
    }
}

// ---------------------------------------------------------------------------
extern "C" void kernel_launch(void* const* d_in, const int* in_sizes, int n_in,
                              void* d_out, int out_size) {
    const float* batch = (const float*)d_in[0];   // [16,1024,1024] f32
    const float* proj  = (const float*)d_in[1];   // [1024,128] f32
    float* out = (float*)d_out;                   // [16,1024,1024] f32
    (void)in_sizes; (void)n_in; (void)out_size;

    static const size_t s1_smem = (size_t)3 * (S1_AS + S1_BS) * sizeof(float);  // 79.9 KB
    static const size_t s2_smem = (size_t)6 * S2_TS * sizeof(float);            // 110.6 KB

    cudaFuncSetAttribute(gemm1_kernel, cudaFuncAttributeMaxDynamicSharedMemorySize, (int)s1_smem);
    cudaFuncSetAttribute(gemm2_kernel, cudaFuncAttributeMaxDynamicSharedMemorySize, (int)s2_smem);

    round_proj_kernel<<<DIM * RANK / 4 / 256, 256>>>(proj);
    gemm1_kernel<<<SEQ * BATCH / 64, 256, s1_smem>>>(batch);
    norms_kernel<<<BATCH * SEQ / 8, 256>>>();
    gemm2_kernel<<<dim3(36, BATCH), 256, s2_smem>>>(out);
}

// round 16
// speedup vs baseline: 1.7778x; 1.0166x over previous
#include <cuda_runtime.h>
#include <cstdint>

// ---------------------------------------------------------------------------
// TwoWordPSDProbe: out[b,i,j] = max(||t_i||^2 + ||t_j||^2 - 2 t_i.t_j, 0)
// t = batch @ proj.  B=16, S=1024, D=1024, R=128.
//
// Legacy tf32 mma.sync (tcgen05 unavailable: harness targets sm_103, not
// sm_103a). Key optimization: t and proj stored in MMA-FRAGMENT-PACKED
// layout so one LDS.128 loads a whole fragment quad:
//   g_tP[(mi*16+ks)*128 + lane*4 + q], lane = g*4+tg:
//     q0=(row mi*16+g,   col ks*8+tg)    q1=(row +8, col tg)
//     q2=(row g,         col tg+4)       q3=(row +8, col tg+4)
// A-fragment = (q0,q1,q2,q3); B-fragments of the SAME quad: even n8 tile
// (b0,b1)=(q0,q2), odd n8 tile (+8 rows) = (q1,q3). One copy serves both
// operands of t.t^T.
// All tf32 roundings explicit (cvt.rna) - HW truncation is biased (R5).
// R14 bug fixed: gemm1's A-prefetch register rotation (rcur=rnx) restored.
// ---------------------------------------------------------------------------

#define BATCH 16
#define SEQ   1024
#define DIM   1024
#define RANK  128
#define MTOT  16384

static __device__ __align__(16) float g_tP[(MTOT / 16) * (RANK / 8) * 128]; // 8 MB
static __device__ __align__(16) float g_projP[8 * 128 * 128];               // 512 KB
static __device__ float g_norms[MTOT];

__constant__ int c_pi[36] = {0,0,0,0,0,0,0,0, 1,1,1,1,1,1,1, 2,2,2,2,2,2,
                             3,3,3,3,3, 4,4,4,4, 5,5,5, 6,6, 7};
__constant__ int c_pj[36] = {0,1,2,3,4,5,6,7, 1,2,3,4,5,6,7, 2,3,4,5,6,7,
                             3,4,5,6,7, 4,5,6,7, 5,6,7, 6,7, 7};

__device__ __forceinline__ unsigned tf32r(float x) {
    unsigned y; asm("cvt.rna.tf32.f32 %0, %1;" : "=r"(y) : "f"(x)); return y;
}
__device__ __forceinline__ float tf32rf(float x) { return __uint_as_float(tf32r(x)); }

__device__ __forceinline__ void mma_tf32(float& d0, float& d1, float& d2, float& d3,
                                         unsigned a0, unsigned a1, unsigned a2, unsigned a3,
                                         unsigned b0, unsigned b1) {
    asm volatile(
        "mma.sync.aligned.m16n8k8.row.col.f32.tf32.tf32.f32 "
        "{%0,%1,%2,%3}, {%4,%5,%6,%7}, {%8,%9}, {%0,%1,%2,%3};"
        : "+f"(d0), "+f"(d1), "+f"(d2), "+f"(d3)
        : "r"(a0), "r"(a1), "r"(a2), "r"(a3), "r"(b0), "r"(b1));
}

__device__ __forceinline__ void cp_async16(void* sptr, const void* gptr) {
    unsigned saddr = (unsigned)__cvta_generic_to_shared(sptr);
    asm volatile("cp.async.cg.shared.global [%0], [%1], 16;\n" :: "r"(saddr), "l"(gptr));
}
#define CP_COMMIT() asm volatile("cp.async.commit_group;\n")
#define CP_WAIT(N)  asm volatile("cp.async.wait_group %0;\n" :: "n"(N))

// ---------------------------------------------------------------------------
// Kernel 0: pack proj (B operand, n=r, k=d) into fragment order, rounded.
// One warp per (ri, ksd) slab.
// ---------------------------------------------------------------------------
__global__ __launch_bounds__(256) void pack_proj(const float* __restrict__ proj) {
    const int warp = threadIdx.x >> 5, lane = threadIdx.x & 31;
    const int slab = blockIdx.x * 8 + warp;       // 0..1023 = ri*128 + ksd
    const int ri = slab >> 7, ksd = slab & 127;
    const int g = lane >> 2, tg = lane & 3;
    const int r0 = ri * 16 + g, r1 = r0 + 8;
    const int d0 = ksd * 8 + tg, d1 = d0 + 4;
    float4 v;
    v.x = tf32rf(proj[(size_t)d0 * RANK + r0]);
    v.y = tf32rf(proj[(size_t)d0 * RANK + r1]);
    v.z = tf32rf(proj[(size_t)d1 * RANK + r0]);
    v.w = tf32rf(proj[(size_t)d1 * RANK + r1]);
    *(float4*)&g_projP[(size_t)slab * 128 + lane * 4] = v;
}

// ---------------------------------------------------------------------------
// Kernel 1: t = batch @ proj  -> g_tP (fragment-packed) + fused norms.
// CTA 64m x 128n, grid 256, 8 warps = 2(m) x 4(n), warp 32x32, K-chunk 32.
// 3-stage ring, one barrier per chunk.
// A: LDG (+1 chunk) -> cvt.rna -> STS (row-major pad 36).
// B: cp.async from g_projP (packed) -> bf via 2x LDS.128 per ks.
// ---------------------------------------------------------------------------
#define S1_AS (64 * 36)     // row-major A stage (floats)
#define S1_BS 4096          // packed B stage: 8 ri x 4 ks x 128
#define S1_CHUNKS (DIM / 32)

__global__ __launch_bounds__(256, 2) void gemm1_kernel(const float* __restrict__ batch) {
    extern __shared__ float smem[];
    float* sA = smem;                   // [3][64][36]
    float* sB = smem + 3 * S1_AS;       // [3][4096]

    const int tid  = threadIdx.x;
    const int warp = tid >> 5, lane = tid & 31;
    const int wm = warp >> 2, wn = warp & 3;      // 2 x 4 warp grid
    const int g  = lane >> 2, tg = lane & 3;
    const int m0 = blockIdx.x * 64;

    float acc[2][4][4];
#pragma unroll
    for (int mt = 0; mt < 2; mt++)
#pragma unroll
        for (int nt = 0; nt < 4; nt++)
#pragma unroll
            for (int v = 0; v < 4; v++) acc[mt][nt][v] = 0.0f;

    const int a_row0 = tid >> 3, a_kk = (tid & 7) * 4;
    const float* aptr0 = batch + (size_t)(m0 + a_row0) * DIM + a_kk;
    const float* aptr1 = batch + (size_t)(m0 + a_row0 + 32) * DIM + a_kk;

    float4 rcur0, rcur1, rnx0, rnx1;

    auto ldg_a = [&](int c, float4& r0, float4& r1) {
        r0 = *(const float4*)(aptr0 + c * 32);
        r1 = *(const float4*)(aptr1 + c * 32);
    };
    auto sts_a = [&](const float4& r0, const float4& r1, int s) {
        float* a = sA + s * S1_AS;
        float4 v0, v1;
        v0.x = tf32rf(r0.x); v0.y = tf32rf(r0.y); v0.z = tf32rf(r0.z); v0.w = tf32rf(r0.w);
        v1.x = tf32rf(r1.x); v1.y = tf32rf(r1.y); v1.z = tf32rf(r1.z); v1.w = tf32rf(r1.w);
        *(float4*)(&a[a_row0 * 36 + a_kk])        = v0;
        *(float4*)(&a[(a_row0 + 32) * 36 + a_kk]) = v1;
    };
    auto cp_b = [&](int c, int s) {
        float* bb = sB + s * S1_BS;
        int j = tid;
#pragma unroll
        for (int i = 0; i < 4; i++) {
            int blk = j >> 7, off = (j & 127) << 2;
            cp_async16(&bb[blk * 512 + off],
                       g_projP + ((size_t)blk * 128 + c * 4) * 128 + off);
            j += 256;
        }
        CP_COMMIT();
    };

    // prologue: chunk0 -> buf0; chunk1 regs
    ldg_a(0, rcur0, rcur1);
    sts_a(rcur0, rcur1, 0);
    cp_b(0, 0);
    ldg_a(1, rcur0, rcur1);

    for (int c = 0; c < S1_CHUNKS; c++) {
        if (c + 1 < S1_CHUNKS) {
            sts_a(rcur0, rcur1, (c + 1) % 3);
            cp_b(c + 1, (c + 1) % 3);
            if (c + 2 < S1_CHUNKS) ldg_a(c + 2, rnx0, rnx1);
            CP_WAIT(1);
        } else {
            CP_WAIT(0);
        }
        __syncthreads();

        const float* a  = sA + (c % 3) * S1_AS;
        const float* bb = sB + (c % 3) * S1_BS;
#pragma unroll
        for (int ks = 0; ks < 4; ks++) {
            const int kb = ks * 8;
            unsigned af[2][4];
#pragma unroll
            for (int mt = 0; mt < 2; mt++) {
                int row = wm * 32 + mt * 16;
                af[mt][0] = __float_as_uint(a[(row + g    ) * 36 + kb + tg    ]);
                af[mt][1] = __float_as_uint(a[(row + g + 8) * 36 + kb + tg    ]);
                af[mt][2] = __float_as_uint(a[(row + g    ) * 36 + kb + tg + 4]);
                af[mt][3] = __float_as_uint(a[(row + g + 8) * 36 + kb + tg + 4]);
            }
#pragma unroll
            for (int p = 0; p < 2; p++) {
                float4 bv = *(const float4*)&bb[((wn * 2 + p) * 4 + ks) * 128 + lane * 4];
                unsigned be0 = __float_as_uint(bv.x), be1 = __float_as_uint(bv.z);
                unsigned bo0 = __float_as_uint(bv.y), bo1 = __float_as_uint(bv.w);
#pragma unroll
                for (int mt = 0; mt < 2; mt++) {
                    mma_tf32(acc[mt][2*p][0], acc[mt][2*p][1], acc[mt][2*p][2], acc[mt][2*p][3],
                             af[mt][0], af[mt][1], af[mt][2], af[mt][3], be0, be1);
                    mma_tf32(acc[mt][2*p+1][0], acc[mt][2*p+1][1], acc[mt][2*p+1][2], acc[mt][2*p+1][3],
                             af[mt][0], af[mt][1], af[mt][2], af[mt][3], bo0, bo1);
                }
            }
        }

        rcur0 = rnx0; rcur1 = rnx1;   // <-- THE R14 FIX: rotate A prefetch regs
    }
    __syncthreads();   // all warps done with pipeline smem

    // ---- epilogue: stage tile in smem (rounded), repack to g_tP, norms ----
    float* tile = smem;   // 64 x 132 floats = 8448 <= 19200 available
#pragma unroll
    for (int mt = 0; mt < 2; mt++) {
#pragma unroll
        for (int nt = 0; nt < 4; nt++) {
            int row = wm * 32 + mt * 16 + g;
            int cb  = wn * 32 + (nt >> 1) * 16 + (nt & 1) * 8 + tg * 2;
            tile[row * 132 + cb]           = tf32rf(acc[mt][nt][0]);
            tile[row * 132 + cb + 1]       = tf32rf(acc[mt][nt][1]);
            tile[(row + 8) * 132 + cb]     = tf32rf(acc[mt][nt][2]);
            tile[(row + 8) * 132 + cb + 1] = tf32rf(acc[mt][nt][3]);
        }
    }
    __syncthreads();

    // repack: 64 slabs (mi 0..3 x ks 0..15); warp handles slabs warp+8*it
#pragma unroll
    for (int it = 0; it < 8; it++) {
        int slab = warp + it * 8;
        int mi = slab >> 4, ks = slab & 15;
        int r0 = mi * 16 + g, c0 = ks * 8 + tg;
        float4 v;
        v.x = tile[r0 * 132 + c0];
        v.y = tile[(r0 + 8) * 132 + c0];
        v.z = tile[r0 * 132 + c0 + 4];
        v.w = tile[(r0 + 8) * 132 + c0 + 4];
        size_t mi_glob = (size_t)(m0 >> 4) + mi;
        *(float4*)&g_tP[(mi_glob * 16 + ks) * 128 + lane * 4] = v;
    }

    // fused norms: thread (row=tid>>2, quarter=tid&3) sums 32 cols
    {
        int row = tid >> 2, q4 = tid & 3;
        float s = 0.0f;
#pragma unroll
        for (int i = 0; i < 8; i++) {
            float4 u = *(const float4*)&tile[row * 132 + q4 * 32 + i * 4];
            s += u.x * u.x + u.y * u.y + u.z * u.z + u.w * u.w;
        }
        s += __shfl_xor_sync(0xFFFFFFFFu, s, 1);
        s += __shfl_xor_sync(0xFFFFFFFFu, s, 2);
        if (q4 == 0) g_norms[m0 + row] = s;
    }
}

// ---------------------------------------------------------------------------
// Kernel 2: upper-triangle tile pairs of t.t^T, mirror via smem transpose.
// CTA 128x128, 4 K-chunks of 32, 3-stage ring. 8 warps = 4(m) x 2(n),
// warp 32x64. Fragments from packed g_tP: 6 LDS.128 per ks.
// ---------------------------------------------------------------------------
#define S2S 4096            // packed stage per side: 8 mi x 4 ks x 128
#define S2_CHUNKS (RANK / 32)

__global__ __launch_bounds__(256, 2) void gemm2_kernel(float* __restrict__ out) {
    extern __shared__ float smem[];
    float* sA = smem;                 // [3][4096]
    float* sB = smem + 3 * S2S;       // [3][4096]
    __shared__ float nI[128], nJ[128];

    const int tid  = threadIdx.x;
    const int warp = tid >> 5, lane = tid & 31;
    const int wm = warp >> 1, wn = warp & 1;
    const int g  = lane >> 2, tg = lane & 3;

    const int b  = blockIdx.y;
    const int bi = c_pi[blockIdx.x];
    const int bj = c_pj[blockIdx.x];

    if (tid < 128)       nI[tid]       = g_norms[b * SEQ + bi * 128 + tid];
    else                 nJ[tid - 128] = g_norms[b * SEQ + bj * 128 + (tid - 128)];

    float acc[2][8][4];
#pragma unroll
    for (int mt = 0; mt < 2; mt++)
#pragma unroll
        for (int nt = 0; nt < 8; nt++)
#pragma unroll
            for (int v = 0; v < 4; v++) acc[mt][nt][v] = 0.0f;

    const int miA = b * 64 + bi * 8;   // global m16-tile base, i-side
    const int miB = b * 64 + bj * 8;

    auto load_chunk = [&](int c, int s) {
        float* a  = sA + s * S2S;
        float* bb = sB + s * S2S;
        int j = tid;
#pragma unroll
        for (int i = 0; i < 4; i++) {
            int blk = j >> 7, off = (j & 127) << 2;
            cp_async16(&a[blk * 512 + off],
                       g_tP + ((size_t)(miA + blk) * 16 + c * 4) * 128 + off);
            cp_async16(&bb[blk * 512 + off],
                       g_tP + ((size_t)(miB + blk) * 16 + c * 4) * 128 + off);
            j += 256;
        }
        CP_COMMIT();
    };

    load_chunk(0, 0);

#pragma unroll
    for (int c = 0; c < S2_CHUNKS; c++) {
        if (c + 1 < S2_CHUNKS) { load_chunk(c + 1, (c + 1) % 3); CP_WAIT(1); }
        else                   { CP_WAIT(0); }
        __syncthreads();

        const float* a  = sA + (c % 3) * S2S;
        const float* bb = sB + (c % 3) * S2S;
#pragma unroll
        for (int ks = 0; ks < 4; ks++) {
            unsigned af[2][4];
#pragma unroll
            for (int mt = 0; mt < 2; mt++) {
                float4 av = *(const float4*)&a[((wm * 2 + mt) * 4 + ks) * 128 + lane * 4];
                af[mt][0] = __float_as_uint(av.x);
                af[mt][1] = __float_as_uint(av.y);
                af[mt][2] = __float_as_uint(av.z);
                af[mt][3] = __float_as_uint(av.w);
            }
#pragma unroll
            for (int p = 0; p < 4; p++) {
                float4 bv = *(const float4*)&bb[((wn * 4 + p) * 4 + ks) * 128 + lane * 4];
                unsigned be0 = __float_as_uint(bv.x), be1 = __float_as_uint(bv.z);
                unsigned bo0 = __float_as_uint(bv.y), bo1 = __float_as_uint(bv.w);
#pragma unroll
                for (int mt = 0; mt < 2; mt++) {
                    mma_tf32(acc[mt][2*p][0], acc[mt][2*p][1], acc[mt][2*p][2], acc[mt][2*p][3],
                             af[mt][0], af[mt][1], af[mt][2], af[mt][3], be0, be1);
                    mma_tf32(acc[mt][2*p+1][0], acc[mt][2*p+1][1], acc[mt][2*p+1][2], acc[mt][2*p+1][3],
                             af[mt][0], af[mt][1], af[mt][2], af[mt][3], bo0, bo1);
                }
            }
        }
    }

    // epilogue: finalize, direct store to (bi,bj)
    float* outb = out + (size_t)b * SEQ * SEQ;
#pragma unroll
    for (int mt = 0; mt < 2; mt++) {
#pragma unroll
        for (int nt = 0; nt < 8; nt++) {
            int r0 = wm * 32 + mt * 16 + g;
            int cb = wn * 64 + (nt >> 1) * 16 + (nt & 1) * 8 + tg * 2;
            float ni0 = nI[r0], ni1 = nI[r0 + 8];
            float nj0 = nJ[cb], nj1 = nJ[cb + 1];
            acc[mt][nt][0] = fmaxf(ni0 + nj0 - 2.0f * acc[mt][nt][0], 0.0f);
            acc[mt][nt][1] = fmaxf(ni0 + nj1 - 2.0f * acc[mt][nt][1], 0.0f);
            acc[mt][nt][2] = fmaxf(ni1 + nj0 - 2.0f * acc[mt][nt][2], 0.0f);
            acc[mt][nt][3] = fmaxf(ni1 + nj1 - 2.0f * acc[mt][nt][3], 0.0f);
            size_t base = (size_t)(bi * 128 + r0) * SEQ + bj * 128 + cb;
            *(float2*)(&outb[base])                   = make_float2(acc[mt][nt][0], acc[mt][nt][1]);
            *(float2*)(&outb[base + (size_t)8 * SEQ]) = make_float2(acc[mt][nt][2], acc[mt][nt][3]);
        }
    }

    // mirror tile (bj,bi) via smem transpose (pad 129)
    if (bi != bj) {
        __syncthreads();
        float* sT = smem;             // 128*129 = 16512 floats <= 24576
#pragma unroll
        for (int mt = 0; mt < 2; mt++) {
#pragma unroll
            for (int nt = 0; nt < 8; nt++) {
                int r0 = wm * 32 + mt * 16 + g;
                int cb = wn * 64 + (nt >> 1) * 16 + (nt & 1) * 8 + tg * 2;
                sT[r0 * 129 + cb]           = acc[mt][nt][0];
                sT[r0 * 129 + cb + 1]       = acc[mt][nt][1];
                sT[(r0 + 8) * 129 + cb]     = acc[mt][nt][2];
                sT[(r0 + 8) * 129 + cb + 1] = acc[mt][nt][3];
            }
        }
        __syncthreads();
        const int colw = tid & 127, rsel = tid >> 7;
#pragma unroll 8
        for (int s = 0; s < 64; s++) {
            int row = s * 2 + rsel;
            outb[(size_t)(bj * 128 + row) * SEQ + bi * 128 + colw] = sT[colw * 129 + row];
        }
    }
}

// ---------------------------------------------------------------------------
extern "C" void kernel_launch(void* const* d_in, const int* in_sizes, int n_in,
                              void* d_out, int out_size) {
    const float* batch = (const float*)d_in[0];   // [16,1024,1024] f32
    const float* proj  = (const float*)d_in[1];   // [1024,128] f32
    float* out = (float*)d_out;                   // [16,1024,1024] f32
    (void)in_sizes; (void)n_in; (void)out_size;

    const size_t s1_smem = (size_t)3 * (S1_AS + S1_BS) * sizeof(float);  // 76.8 KB
    const size_t s2_smem = (size_t)6 * S2S * sizeof(float);              // 98.3 KB

    cudaFuncSetAttribute(gemm1_kernel, cudaFuncAttributeMaxDynamicSharedMemorySize, (int)s1_smem);
    cudaFuncSetAttribute(gemm2_kernel, cudaFuncAttributeMaxDynamicSharedMemorySize, (int)s2_smem);

    pack_proj<<<128, 256>>>(proj);
    gemm1_kernel<<<MTOT / 64, 256, s1_smem>>>(batch);
    gemm2_kernel<<<dim3(36, BATCH), 256, s2_smem>>>(out);
}

// round 17
// speedup vs baseline: 2.6260x; 1.4771x over previous
#include <cuda_runtime.h>
#include <cuda_bf16.h>
#include <cstdint>

// ---------------------------------------------------------------------------
// TwoWordPSDProbe: out[b,i,j] = max(||t_i||^2 + ||t_j||^2 - 2 t_i.t_j, 0)
// t = batch @ proj.  B=16, S=1024, D=1024, R=128.
//
// bf16 mma.sync m16n8k16 (f32 accum) for both GEMMs — 2x MAC/instr and half
// the smem bytes/MAC vs the tf32 version (R16 showed LDS instr count alone
// was not the binder). All roundings are explicit round-to-nearest-even
// (unbiased). t stored bf16-packed in MMA-fragment quads; norms computed
// from the SAME bf16 values so the diagonal is consistent.
//
// Quad layout per (m16-tile, k16-slab): lane l = g*4+tg holds 4 x b32 pairs:
//   q0 = {T[g][16s+2tg], T[g][16s+2tg+1]}      q1 = same rows +8
//   q2 = {T[g][16s+2tg+8], T[g][16s+2tg+9]}    q3 = rows +8
// A-frag = (q0,q1,q2,q3).  B-frags: even n8 tile (q0,q2), odd (q1,q3).
// ---------------------------------------------------------------------------

#define BATCH 16
#define SEQ   1024
#define DIM   1024
#define RANK  128
#define MTOT  16384

static __device__ __align__(16) unsigned g_tP[(MTOT / 16) * (RANK / 16) * 128];  // 4 MB
static __device__ __align__(16) unsigned g_projP[8 * 64 * 128];                  // 256 KB
static __device__ float g_norms[MTOT];

__constant__ int c_pi[36] = {0,0,0,0,0,0,0,0, 1,1,1,1,1,1,1, 2,2,2,2,2,2,
                             3,3,3,3,3, 4,4,4,4, 5,5,5, 6,6, 7};
__constant__ int c_pj[36] = {0,1,2,3,4,5,6,7, 1,2,3,4,5,6,7, 2,3,4,5,6,7,
                             3,4,5,6,7, 4,5,6,7, 5,6,7, 6,7, 7};

__device__ __forceinline__ unsigned pkbf(float lo, float hi) {
    __nv_bfloat162 h;
    h.x = __float2bfloat16_rn(lo);
    h.y = __float2bfloat16_rn(hi);
    return *(unsigned*)&h;
}

__device__ __forceinline__ void mma_bf16(float& d0, float& d1, float& d2, float& d3,
                                         unsigned a0, unsigned a1, unsigned a2, unsigned a3,
                                         unsigned b0, unsigned b1) {
    asm volatile(
        "mma.sync.aligned.m16n8k16.row.col.f32.bf16.bf16.f32 "
        "{%0,%1,%2,%3}, {%4,%5,%6,%7}, {%8,%9}, {%0,%1,%2,%3};"
        : "+f"(d0), "+f"(d1), "+f"(d2), "+f"(d3)
        : "r"(a0), "r"(a1), "r"(a2), "r"(a3), "r"(b0), "r"(b1));
}

__device__ __forceinline__ void cp_async16(void* sptr, const void* gptr) {
    unsigned saddr = (unsigned)__cvta_generic_to_shared(sptr);
    asm volatile("cp.async.cg.shared.global [%0], [%1], 16;\n" :: "r"(saddr), "l"(gptr));
}
#define CP_COMMIT() asm volatile("cp.async.commit_group;\n")
#define CP_WAIT(N)  asm volatile("cp.async.wait_group %0;\n" :: "n"(N))

// ---------------------------------------------------------------------------
// Kernel 0: pack proj -> g_projP[(ri*64 + slab)*128 + lane*4 + q], bf16 pairs.
// CTA covers 32 k-rows x 128 r (= 2 slabs x 8 ri). grid = 32.
// ---------------------------------------------------------------------------
__global__ __launch_bounds__(256) void pack_proj(const float* __restrict__ proj) {
    __shared__ float t[32 * 132];                 // ld=132 -> (8tg+g) banks
    const int tid = threadIdx.x;
    const int k0 = blockIdx.x * 32;
    // coalesced load 32x128 f32
#pragma unroll
    for (int i = 0; i < 4; i++) {
        int f4 = tid + i * 256;                   // float4 id, 0..1023
        int kr = f4 >> 5, c4 = (f4 & 31) * 4;
        *(float4*)&t[kr * 132 + c4] = *(const float4*)&proj[(size_t)(k0 + kr) * RANK + c4];
    }
    __syncthreads();
    const int warp = tid >> 5, lane = tid & 31;
    const int g = lane >> 2, tg = lane & 3;
#pragma unroll
    for (int it = 0; it < 2; it++) {
        int qb = warp + it * 8;                   // 0..15 = sl*8 + ri
        int sl = qb >> 3, ri = qb & 7;
        int kk = sl * 16 + 2 * tg;                // local k row
        int r0 = ri * 16 + g;
        unsigned q0 = pkbf(t[kk * 132 + r0],           t[(kk + 1) * 132 + r0]);
        unsigned q1 = pkbf(t[kk * 132 + r0 + 8],       t[(kk + 1) * 132 + r0 + 8]);
        unsigned q2 = pkbf(t[(kk + 8) * 132 + r0],     t[(kk + 9) * 132 + r0]);
        unsigned q3 = pkbf(t[(kk + 8) * 132 + r0 + 8], t[(kk + 9) * 132 + r0 + 8]);
        uint4 v = make_uint4(q0, q1, q2, q3);
        *(uint4*)&g_projP[((size_t)ri * 64 + (k0 >> 4) + sl) * 128 + lane * 4] = v;
    }
}

// ---------------------------------------------------------------------------
// Kernel 1: t = batch @ proj -> g_tP (bf16 quads) + fused norms.
// CTA 64m x 128n, grid 256, 8 warps = 2(m) x 4(n), warp 32x32.
// K-chunk 64 (4 k16-steps), 16 chunks, 2-stage, 2 barriers/chunk.
// A: LDG f32 (+1 chunk) -> cvt bf16 pairs -> STS.128 (row-major ld=36 b32).
// B: cp.async packed quads from g_projP.
// ---------------------------------------------------------------------------
#define S1_A 2304   // 64 * 36 b32 per stage
#define S1_B 4096   // 8 ri * 4 slabs * 128 b32 per stage
#define S1_CH 16

__global__ __launch_bounds__(256, 2) void gemm1_kernel(const float* __restrict__ batch) {
    extern __shared__ float smem[];
    unsigned* sA = (unsigned*)smem;               // [2][64][36]
    unsigned* sB = sA + 2 * S1_A;                 // [2][4096]

    const int tid  = threadIdx.x;
    const int warp = tid >> 5, lane = tid & 31;
    const int wm = warp >> 2, wn = warp & 3;      // 2 x 4 warps
    const int g  = lane >> 2, tg = lane & 3;
    const int m0 = blockIdx.x * 64;

    float acc[2][4][4];
#pragma unroll
    for (int mt = 0; mt < 2; mt++)
#pragma unroll
        for (int nt = 0; nt < 4; nt++)
#pragma unroll
            for (int v = 0; v < 4; v++) acc[mt][nt][v] = 0.0f;

    const int a_r = tid >> 3;                     // rows a_r, a_r+32
    const int a_k = (tid & 7) * 8;                // 8 f32 per row
    const float* ap0 = batch + (size_t)(m0 + a_r) * DIM + a_k;
    const float* ap1 = batch + (size_t)(m0 + a_r + 32) * DIM + a_k;

    float4 rc[4], rn[4];
    auto ldg_a = [&](int c, float4* r) {
        r[0] = *(const float4*)(ap0 + c * 64);
        r[1] = *(const float4*)(ap0 + c * 64 + 4);
        r[2] = *(const float4*)(ap1 + c * 64);
        r[3] = *(const float4*)(ap1 + c * 64 + 4);
    };
    auto sts_a = [&](const float4* r, int s) {
        unsigned* a = sA + s * S1_A;
        uint4 v0, v1;
        v0.x = pkbf(r[0].x, r[0].y); v0.y = pkbf(r[0].z, r[0].w);
        v0.z = pkbf(r[1].x, r[1].y); v0.w = pkbf(r[1].z, r[1].w);
        v1.x = pkbf(r[2].x, r[2].y); v1.y = pkbf(r[2].z, r[2].w);
        v1.z = pkbf(r[3].x, r[3].y); v1.w = pkbf(r[3].z, r[3].w);
        *(uint4*)&a[a_r * 36 + (a_k >> 1)]        = v0;
        *(uint4*)&a[(a_r + 32) * 36 + (a_k >> 1)] = v1;
    };
    auto cp_b = [&](int c, int s) {
        unsigned* b = sB + s * S1_B;
#pragma unroll
        for (int i = 0; i < 4; i++) {
            int idx = tid + i * 256;              // 0..1023 cp units
            int blk = idx >> 5, off = (idx & 31) * 4;
            int ri = blk >> 2, sl = blk & 3;
            cp_async16(&b[blk * 128 + off],
                       g_projP + ((size_t)ri * 64 + c * 4 + sl) * 128 + off);
        }
        CP_COMMIT();
    };

    ldg_a(0, rc);
    sts_a(rc, 0);
    cp_b(0, 0);
    ldg_a(1, rc);

    for (int c = 0; c < S1_CH; c++) {
        if (c + 1 < S1_CH) {
            sts_a(rc, (c + 1) & 1);
            cp_b(c + 1, (c + 1) & 1);
            if (c + 2 < S1_CH) ldg_a(c + 2, rn);
            CP_WAIT(1);
        } else {
            CP_WAIT(0);
        }
        __syncthreads();

        const unsigned* a = sA + (c & 1) * S1_A;
        const unsigned* b = sB + (c & 1) * S1_B;
#pragma unroll
        for (int sk = 0; sk < 4; sk++) {
            unsigned af[2][4];
#pragma unroll
            for (int mt = 0; mt < 2; mt++) {
                int row = wm * 32 + mt * 16;
                af[mt][0] = a[(row + g    ) * 36 + sk * 8 + tg    ];
                af[mt][1] = a[(row + g + 8) * 36 + sk * 8 + tg    ];
                af[mt][2] = a[(row + g    ) * 36 + sk * 8 + tg + 4];
                af[mt][3] = a[(row + g + 8) * 36 + sk * 8 + tg + 4];
            }
#pragma unroll
            for (int p = 0; p < 2; p++) {
                uint4 q = *(const uint4*)&b[(((wn * 2 + p) * 4 + sk) * 128) + lane * 4];
#pragma unroll
                for (int mt = 0; mt < 2; mt++) {
                    mma_bf16(acc[mt][2*p][0], acc[mt][2*p][1], acc[mt][2*p][2], acc[mt][2*p][3],
                             af[mt][0], af[mt][1], af[mt][2], af[mt][3], q.x, q.z);
                    mma_bf16(acc[mt][2*p+1][0], acc[mt][2*p+1][1], acc[mt][2*p+1][2], acc[mt][2*p+1][3],
                             af[mt][0], af[mt][1], af[mt][2], af[mt][3], q.y, q.w);
                }
            }
        }
        __syncthreads();                          // protect both stages
        rc[0] = rn[0]; rc[1] = rn[1]; rc[2] = rn[2]; rc[3] = rn[3];
    }

    // ---- epilogue: stage bf16-pair tile, repack quads, fused norms ----
    unsigned* tile = (unsigned*)smem;             // [64][68] b32 pairs
#pragma unroll
    for (int mt = 0; mt < 2; mt++) {
#pragma unroll
        for (int nt = 0; nt < 4; nt++) {
            int row = wm * 32 + mt * 16 + g;
            int cp2 = wn * 16 + (nt >> 1) * 8 + (nt & 1) * 4 + tg;  // pair index
            tile[row * 68 + cp2]       = pkbf(acc[mt][nt][0], acc[mt][nt][1]);
            tile[(row + 8) * 68 + cp2] = pkbf(acc[mt][nt][2], acc[mt][nt][3]);
        }
    }
    __syncthreads();

    // repack 32 slabs (mi 0..3 x s 0..7), 4 per warp
#pragma unroll
    for (int it = 0; it < 4; it++) {
        int sb = warp + it * 8;
        int mi = sb >> 3, s = sb & 7;
        int r0 = mi * 16 + g;
        uint4 v;
        v.x = tile[r0 * 68 + s * 8 + tg];
        v.y = tile[(r0 + 8) * 68 + s * 8 + tg];
        v.z = tile[r0 * 68 + s * 8 + tg + 4];
        v.w = tile[(r0 + 8) * 68 + s * 8 + tg + 4];
        *(uint4*)&g_tP[(((size_t)(m0 >> 4) + mi) * 8 + s) * 128 + lane * 4] = v;
    }

    // fused norms from the rounded bf16 values
    {
        int row = tid >> 2, q4 = tid & 3;
        float s = 0.0f;
#pragma unroll
        for (int i = 0; i < 16; i++) {
            __nv_bfloat162 h = *(__nv_bfloat162*)&tile[row * 68 + q4 * 16 + i];
            float x = __low2float(h), y = __high2float(h);
            s += x * x + y * y;
        }
        s += __shfl_xor_sync(0xFFFFFFFFu, s, 1);
        s += __shfl_xor_sync(0xFFFFFFFFu, s, 2);
        if (q4 == 0) g_norms[m0 + row] = s;
    }
}

// ---------------------------------------------------------------------------
// Kernel 2: upper-triangle tile pairs of t.t^T, mirror via smem transpose.
// CTA 128x128, K=128 in 2 chunks of 64 (4 k16-steps each), 2-stage.
// 8 warps = 4(m) x 2(n), warp 32x64. One quad copy serves A and B frags.
// ---------------------------------------------------------------------------
#define S2S 4096    // b32 per stage per side: 8 mi x 4 slabs x 128

__global__ __launch_bounds__(256, 2) void gemm2_kernel(float* __restrict__ out) {
    extern __shared__ float smem[];
    unsigned* sA = (unsigned*)smem;               // [2][4096]
    unsigned* sB = sA + 2 * S2S;                  // [2][4096]
    __shared__ float nI[128], nJ[128];

    const int tid  = threadIdx.x;
    const int warp = tid >> 5, lane = tid & 31;
    const int wm = warp >> 1, wn = warp & 1;
    const int g  = lane >> 2, tg = lane & 3;

    const int b  = blockIdx.y;
    const int bi = c_pi[blockIdx.x];
    const int bj = c_pj[blockIdx.x];

    if (tid < 128)       nI[tid]       = g_norms[b * SEQ + bi * 128 + tid];
    else                 nJ[tid - 128] = g_norms[b * SEQ + bj * 128 + (tid - 128)];

    float acc[2][8][4];
#pragma unroll
    for (int mt = 0; mt < 2; mt++)
#pragma unroll
        for (int nt = 0; nt < 8; nt++)
#pragma unroll
            for (int v = 0; v < 4; v++) acc[mt][nt][v] = 0.0f;

    const int miA = b * 64 + bi * 8;
    const int miB = b * 64 + bj * 8;

    auto load_chunk = [&](int c, int s) {
        unsigned* a  = sA + s * S2S;
        unsigned* bb = sB + s * S2S;
#pragma unroll
        for (int i = 0; i < 4; i++) {
            int idx = tid + i * 256;              // 0..1023
            int blk = idx >> 5, off = (idx & 31) * 4;
            int mi = blk >> 2, sl = blk & 3;
            cp_async16(&a[blk * 128 + off],
                       g_tP + (((size_t)miA + mi) * 8 + c * 4 + sl) * 128 + off);
            cp_async16(&bb[blk * 128 + off],
                       g_tP + (((size_t)miB + mi) * 8 + c * 4 + sl) * 128 + off);
        }
        CP_COMMIT();
    };

    load_chunk(0, 0);

#pragma unroll
    for (int c = 0; c < 2; c++) {
        if (c == 0) { load_chunk(1, 1); CP_WAIT(1); }
        else        { CP_WAIT(0); }
        __syncthreads();

        const unsigned* a  = sA + c * S2S;
        const unsigned* bb = sB + c * S2S;
#pragma unroll
        for (int sk = 0; sk < 4; sk++) {
            uint4 aq[2];
#pragma unroll
            for (int mt = 0; mt < 2; mt++)
                aq[mt] = *(const uint4*)&a[(((wm * 2 + mt) * 4 + sk) * 128) + lane * 4];
#pragma unroll
            for (int p = 0; p < 4; p++) {
                uint4 q = *(const uint4*)&bb[(((wn * 4 + p) * 4 + sk) * 128) + lane * 4];
#pragma unroll
                for (int mt = 0; mt < 2; mt++) {
                    mma_bf16(acc[mt][2*p][0], acc[mt][2*p][1], acc[mt][2*p][2], acc[mt][2*p][3],
                             aq[mt].x, aq[mt].y, aq[mt].z, aq[mt].w, q.x, q.z);
                    mma_bf16(acc[mt][2*p+1][0], acc[mt][2*p+1][1], acc[mt][2*p+1][2], acc[mt][2*p+1][3],
                             aq[mt].x, aq[mt].y, aq[mt].z, aq[mt].w, q.y, q.w);
                }
            }
        }
    }

    // epilogue: finalize, direct store to (bi,bj)
    float* outb = out + (size_t)b * SEQ * SEQ;
#pragma unroll
    for (int mt = 0; mt < 2; mt++) {
#pragma unroll
        for (int nt = 0; nt < 8; nt++) {
            int r0 = wm * 32 + mt * 16 + g;
            int cb = wn * 64 + (nt >> 1) * 16 + (nt & 1) * 8 + tg * 2;
            float ni0 = nI[r0], ni1 = nI[r0 + 8];
            float nj0 = nJ[cb], nj1 = nJ[cb + 1];
            acc[mt][nt][0] = fmaxf(ni0 + nj0 - 2.0f * acc[mt][nt][0], 0.0f);
            acc[mt][nt][1] = fmaxf(ni0 + nj1 - 2.0f * acc[mt][nt][1], 0.0f);
            acc[mt][nt][2] = fmaxf(ni1 + nj0 - 2.0f * acc[mt][nt][2], 0.0f);
            acc[mt][nt][3] = fmaxf(ni1 + nj1 - 2.0f * acc[mt][nt][3], 0.0f);
            size_t base = (size_t)(bi * 128 + r0) * SEQ + bj * 128 + cb;
            *(float2*)(&outb[base])                   = make_float2(acc[mt][nt][0], acc[mt][nt][1]);
            *(float2*)(&outb[base + (size_t)8 * SEQ]) = make_float2(acc[mt][nt][2], acc[mt][nt][3]);
        }
    }

    // mirror tile (bj,bi) via smem transpose (f32, pad 129)
    if (bi != bj) {
        __syncthreads();
        float* sT = smem;                         // 128*129 f32 = 66048 B
#pragma unroll
        for (int mt = 0; mt < 2; mt++) {
#pragma unroll
            for (int nt = 0; nt < 8; nt++) {
                int r0 = wm * 32 + mt * 16 + g;
                int cb = wn * 64 + (nt >> 1) * 16 + (nt & 1) * 8 + tg * 2;
                sT[r0 * 129 + cb]           = acc[mt][nt][0];
                sT[r0 * 129 + cb + 1]       = acc[mt][nt][1];
                sT[(r0 + 8) * 129 + cb]     = acc[mt][nt][2];
                sT[(r0 + 8) * 129 + cb + 1] = acc[mt][nt][3];
            }
        }
        __syncthreads();
        const int colw = tid & 127, rsel = tid >> 7;
#pragma unroll 8
        for (int s = 0; s < 64; s++) {
            int row = s * 2 + rsel;
            outb[(size_t)(bj * 128 + row) * SEQ + bi * 128 + colw] = sT[colw * 129 + row];
        }
    }
}

// ---------------------------------------------------------------------------
extern "C" void kernel_launch(void* const* d_in, const int* in_sizes, int n_in,
                              void* d_out, int out_size) {
    const float* batch = (const float*)d_in[0];   // [16,1024,1024] f32
    const float* proj  = (const float*)d_in[1];   // [1024,128] f32
    float* out = (float*)d_out;                   // [16,1024,1024] f32
    (void)in_sizes; (void)n_in; (void)out_size;

    const size_t s1_smem = (size_t)2 * (S1_A + S1_B) * 4;   // 51.2 KB
    const size_t s2_smem = 128 * 129 * 4;                   // 66.0 KB (>= 64KB tiles)

    cudaFuncSetAttribute(gemm1_kernel, cudaFuncAttributeMaxDynamicSharedMemorySize, (int)s1_smem);
    cudaFuncSetAttribute(gemm2_kernel, cudaFuncAttributeMaxDynamicSharedMemorySize, (int)s2_smem);

    pack_proj<<<DIM / 32, 256>>>(proj);
    gemm1_kernel<<<MTOT / 64, 256, s1_smem>>>(batch);
    gemm2_kernel<<<dim3(36, BATCH), 256, s2_smem>>>(out);
}